// round 10
// baseline (speedup 1.0000x reference)
#include <cuda_runtime.h>
#include <math.h>

#define HID 128
#define NEG 0.2f
#define MAXN 50000
#define MAXE 800000
#define MAXT (MAXE + MAXN)

// ---------------- static scratch (no allocations allowed) ----------------
__device__ float g_h  [MAXN * HID];
__device__ float g_xl [MAXN * HID];
__device__ float g_xr [MAXN * HID];
__device__ float g_loop[MAXN * 32];
__device__ float g_ez  [MAXT];
__device__ int   g_src[MAXE];
__device__ int   g_dst[MAXE];
__device__ int   g_cnt[MAXN];
__device__ int   g_scanA[MAXN];
__device__ int   g_blksum[256];
__device__ int   g_blkoff[256];
__device__ int   g_off[MAXN + 1];
__device__ int   g_cursor[MAXN];
__device__ int   g_eid[MAXT];
__device__ int   g_is64;

// ---------------- small helpers ----------------
__device__ __forceinline__ float lk(float x) { return x > 0.0f ? x : NEG * x; }

__device__ __forceinline__ unsigned int tf32b(float x) {
    unsigned int r;
    asm("cvt.rna.tf32.f32 %0, %1;" : "=r"(r) : "f"(x));
    return r;
}
__device__ __forceinline__ void mma_tf32(float* d, const unsigned int* a,
                                         unsigned int b0, unsigned int b1) {
    asm("mma.sync.aligned.m16n8k8.row.col.f32.tf32.tf32.f32 "
        "{%0,%1,%2,%3}, {%4,%5,%6,%7}, {%8,%9}, {%0,%1,%2,%3};"
        : "+f"(d[0]), "+f"(d[1]), "+f"(d[2]), "+f"(d[3])
        : "r"(a[0]), "r"(a[1]), "r"(a[2]), "r"(a[3]), "r"(b0), "r"(b1));
}
// tf32 hi/lo split: hi = tf32(x), lo = tf32(x - hi)
__device__ __forceinline__ void tf32split(float x, float& hi, float& lo) {
    unsigned int h = tf32b(x);
    hi = __uint_as_float(h);
    lo = __uint_as_float(tf32b(x - hi));
}

// ---------------- dtype detection + index conversion ----------------
__global__ void k_detect(const void* __restrict__ idx, int E, int N) {
    if (threadIdx.x == 0 && blockIdx.x == 0) {
        const long long* p = (const long long*)idx;
        int ok = 1;
        int cnt = 64;
        if (2 * E < 64) cnt = 2 * E;
        for (int i = 0; i < cnt; i++) {
            long long v = p[i];
            if (v < 0 || v >= (long long)N) { ok = 0; break; }
        }
        g_is64 = ok;
    }
}

__global__ void k_prep(const void* __restrict__ idx, int E) {
    int e = blockIdx.x * blockDim.x + threadIdx.x;
    if (e >= E) return;
    if (g_is64) {
        g_src[e] = (int)((const long long*)idx)[e];
        g_dst[e] = (int)((const long long*)idx)[E + e];
    } else {
        g_src[e] = ((const int*)idx)[e];
        g_dst[e] = ((const int*)idx)[E + e];
    }
}

// ---------------- CSR build: count -> scan -> scatter ----------------
__global__ void k_zero_cnt(int N) {
    int i = blockIdx.x * blockDim.x + threadIdx.x;
    if (i < N) g_cnt[i] = 0;
}
__global__ void k_count(int E) {
    int e = blockIdx.x * blockDim.x + threadIdx.x;
    if (e < E) atomicAdd(&g_cnt[g_dst[e]], 1);
}
__global__ void k_scan_local(int N) {
    __shared__ int s[256];
    int b = blockIdx.x, t = threadIdx.x, i = b * 256 + t;
    int v = (i < N) ? g_cnt[i] + 1 : 0;
    s[t] = v;
    __syncthreads();
    for (int o = 1; o < 256; o <<= 1) {
        int x = (t >= o) ? s[t - o] : 0;
        __syncthreads();
        s[t] += x;
        __syncthreads();
    }
    if (i < N) g_scanA[i] = s[t];
    if (t == 255) g_blksum[b] = s[255];
}
__global__ void k_scan_blk(int nblk) {
    __shared__ int s[256];
    int t = threadIdx.x;
    int v = (t < nblk) ? g_blksum[t] : 0;
    s[t] = v;
    __syncthreads();
    for (int o = 1; o < 256; o <<= 1) {
        int x = (t >= o) ? s[t - o] : 0;
        __syncthreads();
        s[t] += x;
        __syncthreads();
    }
    g_blkoff[t] = s[t] - v;   // exclusive
}
__global__ void k_scan_add(int N, int T) {
    int i = blockIdx.x * blockDim.x + threadIdx.x;
    if (i < N) {
        int v = g_cnt[i] + 1;
        int off = g_scanA[i] - v + g_blkoff[i >> 8];
        g_off[i] = off;
        g_cursor[i] = off;
    }
    if (i == 0) g_off[N] = T;
}
__global__ void k_scatter(int E, int T) {
    int e = blockIdx.x * blockDim.x + threadIdx.x;
    if (e >= T) return;
    int d = (e < E) ? g_dst[e] : e - E;
    int pos = atomicAdd(&g_cursor[d], 1);
    g_eid[pos] = e;
}

// ---------------- self-loop attr from CSR (atomic-free) ----------------
__global__ void __launch_bounds__(256) k_loopcsr(const float* __restrict__ ea,
                                                 int E, int N) {
    int w = (blockIdx.x * blockDim.x + threadIdx.x) >> 5;
    int lane = threadIdx.x & 31;
    if (w >= N) return;
    int lo = g_off[w], hi = g_off[w + 1];
    float sum = 0.f;
    int cnt = 0;
    for (int p = lo; p < hi; p++) {
        int eid = g_eid[p];
        if (eid < E) { sum += ea[(size_t)eid * 32 + lane]; cnt++; }
    }
    g_loop[(size_t)w * 32 + lane] = sum / fmaxf((float)cnt, 1.f);
}

// ---------------- tf32 tensor-core GEMM: C[M,128] = A[M,128] @ W[128,128] (+bias) ----
__global__ void __launch_bounds__(256) k_gemm_tc(const float* __restrict__ A,
                                                 const float* __restrict__ W,
                                                 const float* __restrict__ bias,
                                                 float* __restrict__ C, int M) {
    __shared__ float As[128][36];
    __shared__ float Ws[32][136];
    int tid  = threadIdx.x;
    int warp = tid >> 5, lane = tid & 31;
    int gid = lane >> 2, tig = lane & 3;
    int wr = warp & 3, wc = warp >> 2;
    int row0 = blockIdx.x * 128;

    float acc[2][8][4];
#pragma unroll
    for (int ar = 0; ar < 2; ar++)
#pragma unroll
        for (int ac = 0; ac < 8; ac++)
#pragma unroll
            for (int q = 0; q < 4; q++) acc[ar][ac][q] = 0.f;

    for (int kc = 0; kc < 128; kc += 32) {
        {
            int r  = tid >> 1;
            int k4 = (tid & 1) * 16;
            bool ok = (row0 + r) < M;
            const float* ap = A + (size_t)(row0 + r) * 128 + kc + k4;
#pragma unroll
            for (int q = 0; q < 4; q++) {
                float4 v = ok ? *(const float4*)(ap + q * 4)
                              : make_float4(0.f, 0.f, 0.f, 0.f);
                float4 t;
                t.x = __uint_as_float(tf32b(v.x));
                t.y = __uint_as_float(tf32b(v.y));
                t.z = __uint_as_float(tf32b(v.z));
                t.w = __uint_as_float(tf32b(v.w));
                *(float4*)(&As[r][k4 + q * 4]) = t;
            }
        }
        {
            int r  = tid >> 3;
            int c4 = (tid & 7) * 16;
            const float* wp = W + (size_t)(kc + r) * 128 + c4;
#pragma unroll
            for (int q = 0; q < 4; q++) {
                float4 v = *(const float4*)(wp + q * 4);
                float4 t;
                t.x = __uint_as_float(tf32b(v.x));
                t.y = __uint_as_float(tf32b(v.y));
                t.z = __uint_as_float(tf32b(v.z));
                t.w = __uint_as_float(tf32b(v.w));
                *(float4*)(&Ws[r][c4 + q * 4]) = t;
            }
        }
        __syncthreads();

#pragma unroll
        for (int ks = 0; ks < 4; ks++) {
            int k0 = ks * 8;
            unsigned int af[2][4];
#pragma unroll
            for (int ar = 0; ar < 2; ar++) {
                int rb = wr * 32 + ar * 16;
                af[ar][0] = __float_as_uint(As[rb + gid    ][k0 + tig]);
                af[ar][1] = __float_as_uint(As[rb + gid + 8][k0 + tig]);
                af[ar][2] = __float_as_uint(As[rb + gid    ][k0 + tig + 4]);
                af[ar][3] = __float_as_uint(As[rb + gid + 8][k0 + tig + 4]);
            }
#pragma unroll
            for (int ac = 0; ac < 8; ac++) {
                int cb = wc * 64 + ac * 8;
                unsigned int b0 = __float_as_uint(Ws[k0 + tig    ][cb + gid]);
                unsigned int b1 = __float_as_uint(Ws[k0 + tig + 4][cb + gid]);
                mma_tf32(acc[0][ac], af[0], b0, b1);
                mma_tf32(acc[1][ac], af[1], b0, b1);
            }
        }
        __syncthreads();
    }

#pragma unroll
    for (int ar = 0; ar < 2; ar++) {
        int rb = row0 + wr * 32 + ar * 16;
#pragma unroll
        for (int ac = 0; ac < 8; ac++) {
            int col = wc * 64 + ac * 8 + 2 * tig;
            float b0v = bias ? bias[col]     : 0.f;
            float b1v = bias ? bias[col + 1] : 0.f;
            int r0 = rb + gid, r1 = rb + gid + 8;
            if (r0 < M) {
                float2 v = make_float2(acc[ar][ac][0] + b0v, acc[ar][ac][1] + b1v);
                *(float2*)(C + (size_t)r0 * 128 + col) = v;
            }
            if (r1 < M) {
                float2 v = make_float2(acc[ar][ac][2] + b0v, acc[ar][ac][3] + b1v);
                *(float2*)(C + (size_t)r1 * 128 + col) = v;
            }
        }
    }
}

// ---------------- phase A v3: tf32 mma ev GEMM -> smem ev -> fused score -------
// Dynamic smem layout (floats):
//   A hi [128][36] @0, A lo @4608, W hi [32][136] @9216, W lo @13568  (mma stage)
//   ev   [128][132] @0 (overlaps dead A/W after mma)
//   ssrc/sdst (ints) @17920, sp[128][17] @18176  -> total 20352 floats (81.4 KB)
#define ESC_SMF 20352
#define EV_STRIDE 132

__global__ void __launch_bounds__(256, 2) k_escore(const float* __restrict__ ea,
                                                   const float* __restrict__ We,
                                                   const float* __restrict__ att,
                                                   int E, int T) {
    extern __shared__ float sm[];
    float* Ahi = sm;
    float* Alo = sm + 4608;
    float* Whi = sm + 9216;
    float* Wlo = sm + 13568;
    float* ev  = sm;                      // overlaps A/W after mma
    int*   ssrc = (int*)(sm + 17920);
    int*   sdst = ssrc + 128;
    float* sp   = sm + 18176;             // [128][17]

    int tid = threadIdx.x;
    int e0  = blockIdx.x * 128;
    int warp = tid >> 5, lane = tid & 31;
    int gid = lane >> 2, tig = lane & 3;
    int wr = warp & 3, wc = warp >> 2;

    // We 32x128 -> Whi/Wlo (8 thr/row, 16 cols each)
    {
        int r  = tid >> 3;
        int c4 = (tid & 7) * 16;
        const float* wp = We + (size_t)r * 128 + c4;
#pragma unroll
        for (int q = 0; q < 4; q++) {
            float4 v = *(const float4*)(wp + q * 4);
            float h0, l0, h1, l1, h2, l2, h3, l3;
            tf32split(v.x, h0, l0); tf32split(v.y, h1, l1);
            tf32split(v.z, h2, l2); tf32split(v.w, h3, l3);
            int o = r * 136 + c4 + q * 4;
            Whi[o] = h0; Whi[o + 1] = h1; Whi[o + 2] = h2; Whi[o + 3] = h3;
            Wlo[o] = l0; Wlo[o + 1] = l1; Wlo[o + 2] = l2; Wlo[o + 3] = l3;
        }
    }
    // src/dst
    if (tid < 128) {
        int e = e0 + tid;
        if (e < E)      { ssrc[tid] = g_src[e]; sdst[tid] = g_dst[e]; }
        else if (e < T) { ssrc[tid] = sdst[tid] = e - E; }
        else            { ssrc[tid] = sdst[tid] = 0; }
    }
    // ea tile 128x32 -> Ahi/Alo (2 thr/row, 16 k each)
    {
        int r  = tid >> 1;
        int kb = (tid & 1) * 16;
        int e  = e0 + r;
        const float* rowp = (e < E) ? (ea + (size_t)e * 32)
                          : (e < T) ? (g_loop + (size_t)(e - E) * 32)
                                    : (const float*)0;
#pragma unroll
        for (int q = 0; q < 4; q++) {
            float4 v = rowp ? *(const float4*)(rowp + kb + q * 4)
                            : make_float4(0.f, 0.f, 0.f, 0.f);
            float h0, l0, h1, l1, h2, l2, h3, l3;
            tf32split(v.x, h0, l0); tf32split(v.y, h1, l1);
            tf32split(v.z, h2, l2); tf32split(v.w, h3, l3);
            int o = r * 36 + kb + q * 4;
            Ahi[o] = h0; Ahi[o + 1] = h1; Ahi[o + 2] = h2; Ahi[o + 3] = h3;
            Alo[o] = l0; Alo[o + 1] = l1; Alo[o + 2] = l2; Alo[o + 3] = l3;
        }
    }
    __syncthreads();

    // ev GEMM: K=32, 3-mma compensated tf32
    float acc[2][8][4];
#pragma unroll
    for (int ar = 0; ar < 2; ar++)
#pragma unroll
        for (int ac = 0; ac < 8; ac++)
#pragma unroll
            for (int q = 0; q < 4; q++) acc[ar][ac][q] = 0.f;

#pragma unroll
    for (int ks = 0; ks < 4; ks++) {
        int k0 = ks * 8;
        unsigned int ah[2][4], al[2][4];
#pragma unroll
        for (int ar = 0; ar < 2; ar++) {
            int rb = wr * 32 + ar * 16;
            ah[ar][0] = __float_as_uint(Ahi[(rb + gid    ) * 36 + k0 + tig]);
            ah[ar][1] = __float_as_uint(Ahi[(rb + gid + 8) * 36 + k0 + tig]);
            ah[ar][2] = __float_as_uint(Ahi[(rb + gid    ) * 36 + k0 + tig + 4]);
            ah[ar][3] = __float_as_uint(Ahi[(rb + gid + 8) * 36 + k0 + tig + 4]);
            al[ar][0] = __float_as_uint(Alo[(rb + gid    ) * 36 + k0 + tig]);
            al[ar][1] = __float_as_uint(Alo[(rb + gid + 8) * 36 + k0 + tig]);
            al[ar][2] = __float_as_uint(Alo[(rb + gid    ) * 36 + k0 + tig + 4]);
            al[ar][3] = __float_as_uint(Alo[(rb + gid + 8) * 36 + k0 + tig + 4]);
        }
#pragma unroll
        for (int ac = 0; ac < 8; ac++) {
            int cb = wc * 64 + ac * 8;
            unsigned int b0h = __float_as_uint(Whi[(k0 + tig    ) * 136 + cb + gid]);
            unsigned int b1h = __float_as_uint(Whi[(k0 + tig + 4) * 136 + cb + gid]);
            unsigned int b0l = __float_as_uint(Wlo[(k0 + tig    ) * 136 + cb + gid]);
            unsigned int b1l = __float_as_uint(Wlo[(k0 + tig + 4) * 136 + cb + gid]);
#pragma unroll
            for (int ar = 0; ar < 2; ar++) {
                mma_tf32(acc[ar][ac], al[ar], b0h, b1h);
                mma_tf32(acc[ar][ac], ah[ar], b0l, b1l);
                mma_tf32(acc[ar][ac], ah[ar], b0h, b1h);
            }
        }
    }
    __syncthreads();   // A/W tiles dead; reuse as ev

    // store fragments to ev[128][132]
#pragma unroll
    for (int ar = 0; ar < 2; ar++) {
#pragma unroll
        for (int h = 0; h < 2; h++) {
            int row = wr * 32 + ar * 16 + h * 8 + gid;
#pragma unroll
            for (int ac = 0; ac < 8; ac++) {
                int col = wc * 64 + ac * 8 + 2 * tig;
                float2 v = make_float2(acc[ar][ac][2 * h], acc[ar][ac][2 * h + 1]);
                *(float2*)(ev + row * EV_STRIDE + col) = v;
            }
        }
    }
    __syncthreads();

    // fused score epilogue (R6/R8 layout: ty rows, tx col-groups)
    int ty = tid >> 4, tx = tid & 15;
    float4 at0 = *(const float4*)(att + tx * 8);
    float4 at1 = *(const float4*)(att + tx * 8 + 4);
#pragma unroll
    for (int i = 0; i < 8; i++) {
        int r = ty * 8 + i;
        int s = ssrc[r], d = sdst[r];
        const float* xlp = g_xl + (size_t)s * HID + tx * 8;
        const float* xrp = g_xr + (size_t)d * HID + tx * 8;
        float4 xl0 = *(const float4*)(xlp);
        float4 xl1 = *(const float4*)(xlp + 4);
        float4 xr0 = *(const float4*)(xrp);
        float4 xr1 = *(const float4*)(xrp + 4);
        float4 v0 = *(float4*)(ev + r * EV_STRIDE + tx * 8);
        float4 v1 = *(float4*)(ev + r * EV_STRIDE + tx * 8 + 4);
        float p = lk(xl0.x + xr0.x + v0.x) * at0.x
                + lk(xl0.y + xr0.y + v0.y) * at0.y
                + lk(xl0.z + xr0.z + v0.z) * at0.z
                + lk(xl0.w + xr0.w + v0.w) * at0.w
                + lk(xl1.x + xr1.x + v1.x) * at1.x
                + lk(xl1.y + xr1.y + v1.y) * at1.y
                + lk(xl1.z + xr1.z + v1.z) * at1.z
                + lk(xl1.w + xr1.w + v1.w) * at1.w;
        sp[r * 17 + tx] = p;
    }
    __syncthreads();

    if (tid < 128) {
        float sum = 0.f;
#pragma unroll
        for (int j = 0; j < 16; j++) sum += sp[tid * 17 + j];
        int e = e0 + tid;
        if (e < T) g_ez[e] = __expf(sum);
    }
}

// ---------------- phase B: CSR aggregation + norm + bias + silu (no atomics) ----
__global__ void __launch_bounds__(256) k_aggr(const float* __restrict__ bo,
                                              float* __restrict__ out,
                                              int E, int N) {
    int w = (blockIdx.x * blockDim.x + threadIdx.x) >> 5;
    int lane = threadIdx.x & 31;
    if (w >= N) return;
    int lo = g_off[w], hi = g_off[w + 1];
    int c = lane * 4;
    float ax = 0.f, ay = 0.f, az = 0.f, aw = 0.f, den = 0.f;
    for (int p = lo; p < hi; p++) {
        int eid = g_eid[p];
        int s = (eid < E) ? g_src[eid] : w;
        float ez = g_ez[eid];
        float4 xl = *(const float4*)(g_xl + (size_t)s * HID + c);
        ax += ez * xl.x; ay += ez * xl.y; az += ez * xl.z; aw += ez * xl.w;
        den += ez;
    }
    float inv = 1.0f / den;
    float4 b = *(const float4*)(bo + c);
    float vx = ax * inv + b.x;
    float vy = ay * inv + b.y;
    float vz = az * inv + b.z;
    float vw = aw * inv + b.w;
    float4 o;
    o.x = vx / (1.0f + __expf(-vx));
    o.y = vy / (1.0f + __expf(-vy));
    o.z = vz / (1.0f + __expf(-vz));
    o.w = vw / (1.0f + __expf(-vw));
    *(float4*)(out + (size_t)w * HID + c) = o;
}

// ---------------- host orchestration ----------------
extern "C" void kernel_launch(void* const* d_in, const int* in_sizes, int n_in,
                              void* d_out, int out_size) {
    const float* x    = (const float*)d_in[0];
    const void*  eidx = d_in[1];
    const float* ea   = (const float*)d_in[2];
    const float* W_emb = (const float*)d_in[3];
    const float* b_emb = (const float*)d_in[4];
    const float* Wl[2]  = {(const float*)d_in[5],  (const float*)d_in[11]};
    const float* bl[2]  = {(const float*)d_in[6],  (const float*)d_in[12]};
    const float* Wr[2]  = {(const float*)d_in[7],  (const float*)d_in[13]};
    const float* We[2]  = {(const float*)d_in[8],  (const float*)d_in[14]};
    const float* att[2] = {(const float*)d_in[9],  (const float*)d_in[15]};
    const float* bo[2]  = {(const float*)d_in[10], (const float*)d_in[16]};

    int N = in_sizes[0] / HID;
    int E = in_sizes[2] / 32;
    int T = E + N;

    float *p_h, *p_xl, *p_xr;
    cudaGetSymbolAddress((void**)&p_h,  g_h);
    cudaGetSymbolAddress((void**)&p_xl, g_xl);
    cudaGetSymbolAddress((void**)&p_xr, g_xr);

    int gb_n = (N + 127) / 128;
    int nblk = (N + 255) / 256;
    int wb_n = (N * 32 + 255) / 256;

    int esc_smem = ESC_SMF * 4;
    cudaFuncSetAttribute(k_escore, cudaFuncAttributeMaxDynamicSharedMemorySize, esc_smem);

    // launch order: 4th launch (profiled) = embedding GEMM
    k_detect<<<1, 1>>>(eidx, E, N);                                   // 1
    k_prep<<<(E + 255) / 256, 256>>>(eidx, E);                        // 2
    k_zero_cnt<<<nblk, 256>>>(N);                                     // 3
    k_gemm_tc<<<gb_n, 256>>>(x, W_emb, b_emb, p_h, N);                // 4 <- profiled
    // CSR build
    k_count<<<(E + 255) / 256, 256>>>(E);                             // 5
    k_scan_local<<<nblk, 256>>>(N);                                   // 6
    k_scan_blk<<<1, 256>>>(nblk);                                     // 7
    k_scan_add<<<nblk, 256>>>(N, T);                                  // 8
    k_scatter<<<(T + 255) / 256, 256>>>(E, T);                        // 9
    k_loopcsr<<<wb_n, 256>>>(ea, E, N);                               // 10

    int eb = (T + 127) / 128;
    for (int l = 0; l < 2; l++) {
        k_gemm_tc<<<gb_n, 256>>>(p_h, Wl[l], bl[l], p_xl, N);
        k_gemm_tc<<<gb_n, 256>>>(p_h, Wr[l], nullptr, p_xr, N);
        k_escore<<<eb, 256, esc_smem>>>(ea, We[l], att[l], E, T);
        float* dst = (l == 0) ? p_h : (float*)d_out;
        k_aggr<<<wb_n, 256>>>(bo[l], dst, E, N);
    }
}

// round 11
// speedup vs baseline: 1.0666x; 1.0666x over previous
#include <cuda_runtime.h>
#include <math.h>

#define HID 128
#define NEG 0.2f
#define MAXN 50000
#define MAXE 800000
#define MAXT (MAXE + MAXN)

// ---------------- static scratch (no allocations allowed) ----------------
__device__ float g_h  [MAXN * HID];
__device__ float g_xl [MAXN * HID];
__device__ float g_xr [MAXN * HID];
__device__ float g_loop[MAXN * 32];
__device__ float g_ez  [MAXT];
__device__ int   g_src[MAXE];
__device__ int   g_dst[MAXE];
__device__ int   g_cnt[MAXN];
__device__ int   g_scanA[MAXN];
__device__ int   g_blksum[256];
__device__ int   g_blkoff[256];
__device__ int   g_off[MAXN + 1];
__device__ int   g_cursor[MAXN];
__device__ int   g_eid[MAXT];
__device__ int   g_is64;

// ---------------- small helpers ----------------
__device__ __forceinline__ float lk(float x) { return x > 0.0f ? x : NEG * x; }

__device__ __forceinline__ unsigned long long pk2(float x, float y) {
    unsigned long long r;
    asm("mov.b64 %0, {%1, %2};" : "=l"(r) : "f"(x), "f"(y));
    return r;
}
__device__ __forceinline__ void fma2(unsigned long long& d,
                                     unsigned long long a, unsigned long long b) {
    asm("fma.rn.f32x2 %0, %1, %2, %0;" : "+l"(d) : "l"(a), "l"(b));
}
__device__ __forceinline__ float2 up2(unsigned long long v) {
    float2 r;
    asm("mov.b64 {%0, %1}, %2;" : "=f"(r.x), "=f"(r.y) : "l"(v));
    return r;
}
__device__ __forceinline__ unsigned int tf32b(float x) {
    unsigned int r;
    asm("cvt.rna.tf32.f32 %0, %1;" : "=r"(r) : "f"(x));
    return r;
}
__device__ __forceinline__ void mma_tf32(float* d, const unsigned int* a,
                                         unsigned int b0, unsigned int b1) {
    asm("mma.sync.aligned.m16n8k8.row.col.f32.tf32.tf32.f32 "
        "{%0,%1,%2,%3}, {%4,%5,%6,%7}, {%8,%9}, {%0,%1,%2,%3};"
        : "+f"(d[0]), "+f"(d[1]), "+f"(d[2]), "+f"(d[3])
        : "r"(a[0]), "r"(a[1]), "r"(a[2]), "r"(a[3]), "r"(b0), "r"(b1));
}

// ---------------- dtype detection + index conversion (+count fused) ----------
__global__ void k_detect(const void* __restrict__ idx, int E, int N) {
    if (threadIdx.x == 0 && blockIdx.x == 0) {
        const long long* p = (const long long*)idx;
        int ok = 1;
        int cnt = 64;
        if (2 * E < 64) cnt = 2 * E;
        for (int i = 0; i < cnt; i++) {
            long long v = p[i];
            if (v < 0 || v >= (long long)N) { ok = 0; break; }
        }
        g_is64 = ok;
    }
}

__global__ void k_zero_cnt(int N) {
    int i = blockIdx.x * blockDim.x + threadIdx.x;
    if (i < N) g_cnt[i] = 0;
}

// convert indices AND count incoming degree in one pass
__global__ void k_prep(const void* __restrict__ idx, int E) {
    int e = blockIdx.x * blockDim.x + threadIdx.x;
    if (e >= E) return;
    int s, d;
    if (g_is64) {
        s = (int)((const long long*)idx)[e];
        d = (int)((const long long*)idx)[E + e];
    } else {
        s = ((const int*)idx)[e];
        d = ((const int*)idx)[E + e];
    }
    g_src[e] = s;
    g_dst[e] = d;
    atomicAdd(&g_cnt[d], 1);
}

// ---------------- CSR build: scan -> scatter ----------------
__global__ void k_scan_local(int N) {
    __shared__ int s[256];
    int b = blockIdx.x, t = threadIdx.x, i = b * 256 + t;
    int v = (i < N) ? g_cnt[i] + 1 : 0;
    s[t] = v;
    __syncthreads();
    for (int o = 1; o < 256; o <<= 1) {
        int x = (t >= o) ? s[t - o] : 0;
        __syncthreads();
        s[t] += x;
        __syncthreads();
    }
    if (i < N) g_scanA[i] = s[t];
    if (t == 255) g_blksum[b] = s[255];
}
__global__ void k_scan_blk(int nblk) {
    __shared__ int s[256];
    int t = threadIdx.x;
    int v = (t < nblk) ? g_blksum[t] : 0;
    s[t] = v;
    __syncthreads();
    for (int o = 1; o < 256; o <<= 1) {
        int x = (t >= o) ? s[t - o] : 0;
        __syncthreads();
        s[t] += x;
        __syncthreads();
    }
    g_blkoff[t] = s[t] - v;   // exclusive
}
__global__ void k_scan_add(int N, int T) {
    int i = blockIdx.x * blockDim.x + threadIdx.x;
    if (i < N) {
        int v = g_cnt[i] + 1;
        int off = g_scanA[i] - v + g_blkoff[i >> 8];
        g_off[i] = off;
        g_cursor[i] = off;
    }
    if (i == 0) g_off[N] = T;
}
__global__ void k_scatter(int E, int T) {
    int e = blockIdx.x * blockDim.x + threadIdx.x;
    if (e >= T) return;
    int d = (e < E) ? g_dst[e] : e - E;
    int pos = atomicAdd(&g_cursor[d], 1);
    g_eid[pos] = e;
}

// ---------------- self-loop attr from CSR (atomic-free) ----------------
__global__ void __launch_bounds__(256) k_loopcsr(const float* __restrict__ ea,
                                                 int E, int N) {
    int w = (blockIdx.x * blockDim.x + threadIdx.x) >> 5;
    int lane = threadIdx.x & 31;
    if (w >= N) return;
    int lo = g_off[w], hi = g_off[w + 1];
    float sum = 0.f;
    int cnt = 0;
    for (int p = lo; p < hi; p++) {
        int eid = g_eid[p];
        if (eid < E) { sum += ea[(size_t)eid * 32 + lane]; cnt++; }
    }
    g_loop[(size_t)w * 32 + lane] = sum / fmaxf((float)cnt, 1.f);
}

// ---------------- tf32 tensor-core GEMM: C[M,128] = A[M,128] @ W[128,128] (+bias) ----
__global__ void __launch_bounds__(256) k_gemm_tc(const float* __restrict__ A,
                                                 const float* __restrict__ W,
                                                 const float* __restrict__ bias,
                                                 float* __restrict__ C, int M) {
    __shared__ float As[128][36];
    __shared__ float Ws[32][136];
    int tid  = threadIdx.x;
    int warp = tid >> 5, lane = tid & 31;
    int gid = lane >> 2, tig = lane & 3;
    int wr = warp & 3, wc = warp >> 2;
    int row0 = blockIdx.x * 128;

    float acc[2][8][4];
#pragma unroll
    for (int ar = 0; ar < 2; ar++)
#pragma unroll
        for (int ac = 0; ac < 8; ac++)
#pragma unroll
            for (int q = 0; q < 4; q++) acc[ar][ac][q] = 0.f;

    for (int kc = 0; kc < 128; kc += 32) {
        {
            int r  = tid >> 1;
            int k4 = (tid & 1) * 16;
            bool ok = (row0 + r) < M;
            const float* ap = A + (size_t)(row0 + r) * 128 + kc + k4;
#pragma unroll
            for (int q = 0; q < 4; q++) {
                float4 v = ok ? *(const float4*)(ap + q * 4)
                              : make_float4(0.f, 0.f, 0.f, 0.f);
                float4 t;
                t.x = __uint_as_float(tf32b(v.x));
                t.y = __uint_as_float(tf32b(v.y));
                t.z = __uint_as_float(tf32b(v.z));
                t.w = __uint_as_float(tf32b(v.w));
                *(float4*)(&As[r][k4 + q * 4]) = t;
            }
        }
        {
            int r  = tid >> 3;
            int c4 = (tid & 7) * 16;
            const float* wp = W + (size_t)(kc + r) * 128 + c4;
#pragma unroll
            for (int q = 0; q < 4; q++) {
                float4 v = *(const float4*)(wp + q * 4);
                float4 t;
                t.x = __uint_as_float(tf32b(v.x));
                t.y = __uint_as_float(tf32b(v.y));
                t.z = __uint_as_float(tf32b(v.z));
                t.w = __uint_as_float(tf32b(v.w));
                *(float4*)(&Ws[r][c4 + q * 4]) = t;
            }
        }
        __syncthreads();

#pragma unroll
        for (int ks = 0; ks < 4; ks++) {
            int k0 = ks * 8;
            unsigned int af[2][4];
#pragma unroll
            for (int ar = 0; ar < 2; ar++) {
                int rb = wr * 32 + ar * 16;
                af[ar][0] = __float_as_uint(As[rb + gid    ][k0 + tig]);
                af[ar][1] = __float_as_uint(As[rb + gid + 8][k0 + tig]);
                af[ar][2] = __float_as_uint(As[rb + gid    ][k0 + tig + 4]);
                af[ar][3] = __float_as_uint(As[rb + gid + 8][k0 + tig + 4]);
            }
#pragma unroll
            for (int ac = 0; ac < 8; ac++) {
                int cb = wc * 64 + ac * 8;
                unsigned int b0 = __float_as_uint(Ws[k0 + tig    ][cb + gid]);
                unsigned int b1 = __float_as_uint(Ws[k0 + tig + 4][cb + gid]);
                mma_tf32(acc[0][ac], af[0], b0, b1);
                mma_tf32(acc[1][ac], af[1], b0, b1);
            }
        }
        __syncthreads();
    }

#pragma unroll
    for (int ar = 0; ar < 2; ar++) {
        int rb = row0 + wr * 32 + ar * 16;
#pragma unroll
        for (int ac = 0; ac < 8; ac++) {
            int col = wc * 64 + ac * 8 + 2 * tig;
            float b0v = bias ? bias[col]     : 0.f;
            float b1v = bias ? bias[col + 1] : 0.f;
            int r0 = rb + gid, r1 = rb + gid + 8;
            if (r0 < M) {
                float2 v = make_float2(acc[ar][ac][0] + b0v, acc[ar][ac][1] + b1v);
                *(float2*)(C + (size_t)r0 * 128 + col) = v;
            }
            if (r1 < M) {
                float2 v = make_float2(acc[ar][ac][2] + b0v, acc[ar][ac][3] + b1v);
                *(float2*)(C + (size_t)r1 * 128 + col) = v;
            }
        }
    }
}

// ---------------- fused xl/xr GEMM: one A tile, two weight matrices ----------
// 512 threads, block tile 128 rows x 256 cols (xl cols 0-127 from Wl+bl,
// xr cols 0-127 from Wr). 16 warps: wr = warp&3 (row quarter), wc = warp>>2:
// wc 0,1 -> xl halves; wc 2,3 -> xr halves.
// Dynamic smem floats: As[128][36] @0, Wsl[32][136] @4608, Wsr @8960 -> 13312
#define LR_SMF 13312

__global__ void __launch_bounds__(512) k_gemm_lr(const float* __restrict__ A,
                                                 const float* __restrict__ Wlp,
                                                 const float* __restrict__ blp,
                                                 const float* __restrict__ Wrp,
                                                 float* __restrict__ Cl,
                                                 float* __restrict__ Cr, int M) {
    extern __shared__ float smlr[];
    float* As  = smlr;           // [128][36]
    float* Wsl = smlr + 4608;    // [32][136]
    float* Wsr = smlr + 8960;    // [32][136]
    int tid  = threadIdx.x;
    int warp = tid >> 5, lane = tid & 31;
    int gid = lane >> 2, tig = lane & 3;
    int wr = warp & 3, wc = warp >> 2;       // wc 0..3
    int row0 = blockIdx.x * 128;
    const float* Wsrc = (wc < 2) ? Wsl : Wsr;
    int cbase = (wc & 1) * 64;

    float acc[2][8][4];
#pragma unroll
    for (int ar = 0; ar < 2; ar++)
#pragma unroll
        for (int ac = 0; ac < 8; ac++)
#pragma unroll
            for (int q = 0; q < 4; q++) acc[ar][ac][q] = 0.f;

    for (int kc = 0; kc < 128; kc += 32) {
        // A chunk 128x32: 4 thr/row, 8 k each
        {
            int r  = tid >> 2;
            int k4 = (tid & 3) * 8;
            bool ok = (row0 + r) < M;
            const float* ap = A + (size_t)(row0 + r) * 128 + kc + k4;
#pragma unroll
            for (int q = 0; q < 2; q++) {
                float4 v = ok ? *(const float4*)(ap + q * 4)
                              : make_float4(0.f, 0.f, 0.f, 0.f);
                float4 t;
                t.x = __uint_as_float(tf32b(v.x));
                t.y = __uint_as_float(tf32b(v.y));
                t.z = __uint_as_float(tf32b(v.z));
                t.w = __uint_as_float(tf32b(v.w));
                *(float4*)(&As[r * 36 + k4 + q * 4]) = t;
            }
        }
        // Wl + Wr chunks 32x128 each: 16 thr/row, 8 cols each
        {
            int r  = tid >> 4;
            int c8 = (tid & 15) * 8;
            const float* wlp_ = Wlp + (size_t)(kc + r) * 128 + c8;
            const float* wrp_ = Wrp + (size_t)(kc + r) * 128 + c8;
#pragma unroll
            for (int q = 0; q < 2; q++) {
                float4 v = *(const float4*)(wlp_ + q * 4);
                float4 t;
                t.x = __uint_as_float(tf32b(v.x));
                t.y = __uint_as_float(tf32b(v.y));
                t.z = __uint_as_float(tf32b(v.z));
                t.w = __uint_as_float(tf32b(v.w));
                *(float4*)(&Wsl[r * 136 + c8 + q * 4]) = t;
                float4 u = *(const float4*)(wrp_ + q * 4);
                float4 s;
                s.x = __uint_as_float(tf32b(u.x));
                s.y = __uint_as_float(tf32b(u.y));
                s.z = __uint_as_float(tf32b(u.z));
                s.w = __uint_as_float(tf32b(u.w));
                *(float4*)(&Wsr[r * 136 + c8 + q * 4]) = s;
            }
        }
        __syncthreads();

#pragma unroll
        for (int ks = 0; ks < 4; ks++) {
            int k0 = ks * 8;
            unsigned int af[2][4];
#pragma unroll
            for (int ar = 0; ar < 2; ar++) {
                int rb = wr * 32 + ar * 16;
                af[ar][0] = __float_as_uint(As[(rb + gid    ) * 36 + k0 + tig]);
                af[ar][1] = __float_as_uint(As[(rb + gid + 8) * 36 + k0 + tig]);
                af[ar][2] = __float_as_uint(As[(rb + gid    ) * 36 + k0 + tig + 4]);
                af[ar][3] = __float_as_uint(As[(rb + gid + 8) * 36 + k0 + tig + 4]);
            }
#pragma unroll
            for (int ac = 0; ac < 8; ac++) {
                int cb = cbase + ac * 8;
                unsigned int b0 = __float_as_uint(Wsrc[(k0 + tig    ) * 136 + cb + gid]);
                unsigned int b1 = __float_as_uint(Wsrc[(k0 + tig + 4) * 136 + cb + gid]);
                mma_tf32(acc[0][ac], af[0], b0, b1);
                mma_tf32(acc[1][ac], af[1], b0, b1);
            }
        }
        __syncthreads();
    }

    float* Cdst = (wc < 2) ? Cl : Cr;
    const float* bp = (wc < 2) ? blp : (const float*)0;
#pragma unroll
    for (int ar = 0; ar < 2; ar++) {
        int rb = row0 + wr * 32 + ar * 16;
#pragma unroll
        for (int ac = 0; ac < 8; ac++) {
            int col = cbase + ac * 8 + 2 * tig;
            float b0v = bp ? bp[col]     : 0.f;
            float b1v = bp ? bp[col + 1] : 0.f;
            int r0 = rb + gid, r1 = rb + gid + 8;
            if (r0 < M) {
                float2 v = make_float2(acc[ar][ac][0] + b0v, acc[ar][ac][1] + b1v);
                *(float2*)(Cdst + (size_t)r0 * 128 + col) = v;
            }
            if (r1 < M) {
                float2 v = make_float2(acc[ar][ac][2] + b0v, acc[ar][ac][3] + b1v);
                *(float2*)(Cdst + (size_t)r1 * 128 + col) = v;
            }
        }
    }
}

// ---------------- phase A: edge GEMM + score -> ez (no atomics, R8 form) -------
__global__ void __launch_bounds__(256, 2) k_escore(const float* __restrict__ ea,
                                                   const float* __restrict__ We,
                                                   const float* __restrict__ att,
                                                   int E, int T) {
    __shared__ float As[32][128];    // [k][edge-row]
    __shared__ float Ws[32][128];    // [k][col]
    __shared__ int   ssrc[128], sdst[128];
    __shared__ float sp[128][17];    // per-row logit partials

    int tid = threadIdx.x;
    int e0  = blockIdx.x * 128;
    int ty = tid >> 4, tx = tid & 15;

    {
        const float4* src = (const float4*)We;
        float4* dstp = (float4*)&Ws[0][0];
#pragma unroll
        for (int q = 0; q < 4; q++) dstp[tid + q * 256] = src[tid + q * 256];
    }
    if (tid < 128) {
        int e = e0 + tid;
        if (e < E)      { ssrc[tid] = g_src[e]; sdst[tid] = g_dst[e]; }
        else if (e < T) { ssrc[tid] = sdst[tid] = e - E; }
        else            { ssrc[tid] = sdst[tid] = 0; }
    }
    {
        int arow = tid >> 1;
        int kb   = (tid & 1) * 16;
        int e    = e0 + arow;
        const float* rowp = (e < E) ? (ea + (size_t)e * 32)
                          : (e < T) ? (g_loop + (size_t)(e - E) * 32)
                                    : (const float*)0;
#pragma unroll
        for (int q = 0; q < 4; q++) {
            float4 v = rowp ? *(const float4*)(rowp + kb + q * 4)
                            : make_float4(0.f, 0.f, 0.f, 0.f);
            As[kb + q * 4 + 0][arow] = v.x;
            As[kb + q * 4 + 1][arow] = v.y;
            As[kb + q * 4 + 2][arow] = v.z;
            As[kb + q * 4 + 3][arow] = v.w;
        }
    }
    __syncthreads();

    unsigned long long acc2[8][4];
#pragma unroll
    for (int i = 0; i < 8; i++)
#pragma unroll
        for (int j = 0; j < 4; j++) acc2[i][j] = 0ULL;

#pragma unroll
    for (int k = 0; k < 32; k++) {
        float a[8];
        unsigned long long b2[4];
        *(float4*)(a)     = *(float4*)(&As[k][ty * 8]);
        *(float4*)(a + 4) = *(float4*)(&As[k][ty * 8 + 4]);
        const unsigned long long* wp = (const unsigned long long*)(&Ws[k][tx * 8]);
        b2[0] = wp[0]; b2[1] = wp[1]; b2[2] = wp[2]; b2[3] = wp[3];
#pragma unroll
        for (int i = 0; i < 8; i++) {
            unsigned long long pa = pk2(a[i], a[i]);
#pragma unroll
            for (int j = 0; j < 4; j++) fma2(acc2[i][j], pa, b2[j]);
        }
    }

    float4 at0 = *(const float4*)(att + tx * 8);
    float4 at1 = *(const float4*)(att + tx * 8 + 4);
#pragma unroll
    for (int i = 0; i < 8; i++) {
        int r = ty * 8 + i;
        int s = ssrc[r], d = sdst[r];
        const float* xlp = g_xl + (size_t)s * HID + tx * 8;
        const float* xrp = g_xr + (size_t)d * HID + tx * 8;
        float4 xl0 = *(const float4*)(xlp);
        float4 xl1 = *(const float4*)(xlp + 4);
        float4 xr0 = *(const float4*)(xrp);
        float4 xr1 = *(const float4*)(xrp + 4);
        float2 v0 = up2(acc2[i][0]);
        float2 v1 = up2(acc2[i][1]);
        float2 v2 = up2(acc2[i][2]);
        float2 v3 = up2(acc2[i][3]);
        float p = lk(xl0.x + xr0.x + v0.x) * at0.x
                + lk(xl0.y + xr0.y + v0.y) * at0.y
                + lk(xl0.z + xr0.z + v1.x) * at0.z
                + lk(xl0.w + xr0.w + v1.y) * at0.w
                + lk(xl1.x + xr1.x + v2.x) * at1.x
                + lk(xl1.y + xr1.y + v2.y) * at1.y
                + lk(xl1.z + xr1.z + v3.x) * at1.z
                + lk(xl1.w + xr1.w + v3.y) * at1.w;
        sp[r][tx] = p;
    }
    __syncthreads();

    if (tid < 128) {
        float sum = 0.f;
#pragma unroll
        for (int j = 0; j < 16; j++) sum += sp[tid][j];
        int e = e0 + tid;
        if (e < T) g_ez[e] = __expf(sum);
    }
}

// ---------------- phase B: CSR aggregation + norm + bias + silu (no atomics) ----
__global__ void __launch_bounds__(256) k_aggr(const float* __restrict__ bo,
                                              float* __restrict__ out,
                                              int E, int N) {
    int w = (blockIdx.x * blockDim.x + threadIdx.x) >> 5;
    int lane = threadIdx.x & 31;
    if (w >= N) return;
    int lo = g_off[w], hi = g_off[w + 1];
    int c = lane * 4;
    float ax = 0.f, ay = 0.f, az = 0.f, aw = 0.f, den = 0.f;
    for (int p = lo; p < hi; p++) {
        int eid = g_eid[p];
        int s = (eid < E) ? g_src[eid] : w;
        float ez = g_ez[eid];
        float4 xl = *(const float4*)(g_xl + (size_t)s * HID + c);
        ax += ez * xl.x; ay += ez * xl.y; az += ez * xl.z; aw += ez * xl.w;
        den += ez;
    }
    float inv = 1.0f / den;
    float4 b = *(const float4*)(bo + c);
    float vx = ax * inv + b.x;
    float vy = ay * inv + b.y;
    float vz = az * inv + b.z;
    float vw = aw * inv + b.w;
    float4 o;
    o.x = vx / (1.0f + __expf(-vx));
    o.y = vy / (1.0f + __expf(-vy));
    o.z = vz / (1.0f + __expf(-vz));
    o.w = vw / (1.0f + __expf(-vw));
    *(float4*)(out + (size_t)w * HID + c) = o;
}

// ---------------- host orchestration ----------------
extern "C" void kernel_launch(void* const* d_in, const int* in_sizes, int n_in,
                              void* d_out, int out_size) {
    const float* x    = (const float*)d_in[0];
    const void*  eidx = d_in[1];
    const float* ea   = (const float*)d_in[2];
    const float* W_emb = (const float*)d_in[3];
    const float* b_emb = (const float*)d_in[4];
    const float* Wl[2]  = {(const float*)d_in[5],  (const float*)d_in[11]};
    const float* bl[2]  = {(const float*)d_in[6],  (const float*)d_in[12]};
    const float* Wr[2]  = {(const float*)d_in[7],  (const float*)d_in[13]};
    const float* We[2]  = {(const float*)d_in[8],  (const float*)d_in[14]};
    const float* att[2] = {(const float*)d_in[9],  (const float*)d_in[15]};
    const float* bo[2]  = {(const float*)d_in[10], (const float*)d_in[16]};

    int N = in_sizes[0] / HID;
    int E = in_sizes[2] / 32;
    int T = E + N;

    float *p_h, *p_xl, *p_xr;
    cudaGetSymbolAddress((void**)&p_h,  g_h);
    cudaGetSymbolAddress((void**)&p_xl, g_xl);
    cudaGetSymbolAddress((void**)&p_xr, g_xr);

    int gb_n = (N + 127) / 128;
    int nblk = (N + 255) / 256;
    int wb_n = (N * 32 + 255) / 256;

    int lr_smem = LR_SMF * 4;   // 53 KB
    cudaFuncSetAttribute(k_gemm_lr, cudaFuncAttributeMaxDynamicSharedMemorySize, lr_smem);

    k_detect<<<1, 1>>>(eidx, E, N);                                   // 1
    k_zero_cnt<<<nblk, 256>>>(N);                                     // 2
    k_prep<<<(E + 255) / 256, 256>>>(eidx, E);                        // 3 (conv+count)
    k_gemm_tc<<<gb_n, 256>>>(x, W_emb, b_emb, p_h, N);                // 4 <- profiled
    k_scan_local<<<nblk, 256>>>(N);                                   // 5
    k_scan_blk<<<1, 256>>>(nblk);                                     // 6
    k_scan_add<<<nblk, 256>>>(N, T);                                  // 7
    k_scatter<<<(T + 255) / 256, 256>>>(E, T);                        // 8
    k_loopcsr<<<wb_n, 256>>>(ea, E, N);                               // 9

    int eb = (T + 127) / 128;
    for (int l = 0; l < 2; l++) {
        k_gemm_lr<<<gb_n, 512, lr_smem>>>(p_h, Wl[l], bl[l], Wr[l], p_xl, p_xr, N);
        k_escore<<<eb, 256>>>(ea, We[l], att[l], E, T);
        float* dst = (l == 0) ? p_h : (float*)d_out;
        k_aggr<<<wb_n, 256>>>(bo[l], dst, E, N);
    }
}

// round 12
// speedup vs baseline: 1.0987x; 1.0301x over previous
#include <cuda_runtime.h>
#include <math.h>

#define HID 128
#define NEG 0.2f
#define MAXN 50000
#define MAXE 800000
#define MAXT (MAXE + MAXN)

// ---------------- static scratch (no allocations allowed) ----------------
__device__ float g_h  [MAXN * HID];
__device__ float g_xl [MAXN * HID];
__device__ float g_xr [MAXN * HID];
__device__ float g_loop[MAXN * 32];
__device__ float g_ez  [MAXT];     // indexed by CSR position
__device__ int   g_srcs[MAXT];     // src per CSR position
__device__ int   g_src[MAXE];
__device__ int   g_dst[MAXE];
__device__ int   g_cnt[MAXN];
__device__ int   g_scanA[MAXN];
__device__ int   g_blksum[256];
__device__ int   g_blkoff[256];
__device__ int   g_off[MAXN + 1];
__device__ int   g_cursor[MAXN];
__device__ int   g_eid[MAXT];
__device__ int   g_is64;

// ---------------- small helpers ----------------
__device__ __forceinline__ float lk(float x) { return x > 0.0f ? x : NEG * x; }

__device__ __forceinline__ unsigned long long pk2(float x, float y) {
    unsigned long long r;
    asm("mov.b64 %0, {%1, %2};" : "=l"(r) : "f"(x), "f"(y));
    return r;
}
__device__ __forceinline__ void fma2(unsigned long long& d,
                                     unsigned long long a, unsigned long long b) {
    asm("fma.rn.f32x2 %0, %1, %2, %0;" : "+l"(d) : "l"(a), "l"(b));
}
__device__ __forceinline__ float2 up2(unsigned long long v) {
    float2 r;
    asm("mov.b64 {%0, %1}, %2;" : "=f"(r.x), "=f"(r.y) : "l"(v));
    return r;
}
__device__ __forceinline__ unsigned int tf32b(float x) {
    unsigned int r;
    asm("cvt.rna.tf32.f32 %0, %1;" : "=r"(r) : "f"(x));
    return r;
}
__device__ __forceinline__ void mma_tf32(float* d, const unsigned int* a,
                                         unsigned int b0, unsigned int b1) {
    asm("mma.sync.aligned.m16n8k8.row.col.f32.tf32.tf32.f32 "
        "{%0,%1,%2,%3}, {%4,%5,%6,%7}, {%8,%9}, {%0,%1,%2,%3};"
        : "+f"(d[0]), "+f"(d[1]), "+f"(d[2]), "+f"(d[3])
        : "r"(a[0]), "r"(a[1]), "r"(a[2]), "r"(a[3]), "r"(b0), "r"(b1));
}

// ---------------- dtype detection + index conversion (+count fused) ----------
__global__ void k_detect(const void* __restrict__ idx, int E, int N) {
    if (threadIdx.x == 0 && blockIdx.x == 0) {
        const long long* p = (const long long*)idx;
        int ok = 1;
        int cnt = 64;
        if (2 * E < 64) cnt = 2 * E;
        for (int i = 0; i < cnt; i++) {
            long long v = p[i];
            if (v < 0 || v >= (long long)N) { ok = 0; break; }
        }
        g_is64 = ok;
    }
}

__global__ void k_zero_cnt(int N) {
    int i = blockIdx.x * blockDim.x + threadIdx.x;
    if (i < N) g_cnt[i] = 0;
}

// convert indices AND count incoming degree in one pass
__global__ void k_prep(const void* __restrict__ idx, int E) {
    int e = blockIdx.x * blockDim.x + threadIdx.x;
    if (e >= E) return;
    int s, d;
    if (g_is64) {
        s = (int)((const long long*)idx)[e];
        d = (int)((const long long*)idx)[E + e];
    } else {
        s = ((const int*)idx)[e];
        d = ((const int*)idx)[E + e];
    }
    g_src[e] = s;
    g_dst[e] = d;
    atomicAdd(&g_cnt[d], 1);
}

// ---------------- CSR build: scan -> scatter ----------------
__global__ void k_scan_local(int N) {
    __shared__ int s[256];
    int b = blockIdx.x, t = threadIdx.x, i = b * 256 + t;
    int v = (i < N) ? g_cnt[i] + 1 : 0;
    s[t] = v;
    __syncthreads();
    for (int o = 1; o < 256; o <<= 1) {
        int x = (t >= o) ? s[t - o] : 0;
        __syncthreads();
        s[t] += x;
        __syncthreads();
    }
    if (i < N) g_scanA[i] = s[t];
    if (t == 255) g_blksum[b] = s[255];
}
__global__ void k_scan_blk(int nblk) {
    __shared__ int s[256];
    int t = threadIdx.x;
    int v = (t < nblk) ? g_blksum[t] : 0;
    s[t] = v;
    __syncthreads();
    for (int o = 1; o < 256; o <<= 1) {
        int x = (t >= o) ? s[t - o] : 0;
        __syncthreads();
        s[t] += x;
        __syncthreads();
    }
    g_blkoff[t] = s[t] - v;   // exclusive
}
__global__ void k_scan_add(int N, int T) {
    int i = blockIdx.x * blockDim.x + threadIdx.x;
    if (i < N) {
        int v = g_cnt[i] + 1;
        int off = g_scanA[i] - v + g_blkoff[i >> 8];
        g_off[i] = off;
        g_cursor[i] = off;
    }
    if (i == 0) g_off[N] = T;
}
__global__ void k_scatter(int E, int T) {
    int e = blockIdx.x * blockDim.x + threadIdx.x;
    if (e >= T) return;
    int d = (e < E) ? g_dst[e] : e - E;
    int pos = atomicAdd(&g_cursor[d], 1);
    g_eid[pos] = e;
}

// ---------------- self-loop attr from CSR (atomic-free) ----------------
__global__ void __launch_bounds__(256) k_loopcsr(const float* __restrict__ ea,
                                                 int E, int N) {
    int w = (blockIdx.x * blockDim.x + threadIdx.x) >> 5;
    int lane = threadIdx.x & 31;
    if (w >= N) return;
    int lo = g_off[w], hi = g_off[w + 1];
    float sum = 0.f;
    int cnt = 0;
    for (int p = lo; p < hi; p++) {
        int eid = g_eid[p];
        if (eid < E) { sum += ea[(size_t)eid * 32 + lane]; cnt++; }
    }
    g_loop[(size_t)w * 32 + lane] = sum / fmaxf((float)cnt, 1.f);
}

// ---------------- tf32 tensor-core GEMM: C[M,128] = A[M,128] @ W[128,128] (+bias) ----
__global__ void __launch_bounds__(256) k_gemm_tc(const float* __restrict__ A,
                                                 const float* __restrict__ W,
                                                 const float* __restrict__ bias,
                                                 float* __restrict__ C, int M) {
    __shared__ float As[128][36];
    __shared__ float Ws[32][136];
    int tid  = threadIdx.x;
    int warp = tid >> 5, lane = tid & 31;
    int gid = lane >> 2, tig = lane & 3;
    int wr = warp & 3, wc = warp >> 2;
    int row0 = blockIdx.x * 128;

    float acc[2][8][4];
#pragma unroll
    for (int ar = 0; ar < 2; ar++)
#pragma unroll
        for (int ac = 0; ac < 8; ac++)
#pragma unroll
            for (int q = 0; q < 4; q++) acc[ar][ac][q] = 0.f;

    for (int kc = 0; kc < 128; kc += 32) {
        {
            int r  = tid >> 1;
            int k4 = (tid & 1) * 16;
            bool ok = (row0 + r) < M;
            const float* ap = A + (size_t)(row0 + r) * 128 + kc + k4;
#pragma unroll
            for (int q = 0; q < 4; q++) {
                float4 v = ok ? *(const float4*)(ap + q * 4)
                              : make_float4(0.f, 0.f, 0.f, 0.f);
                float4 t;
                t.x = __uint_as_float(tf32b(v.x));
                t.y = __uint_as_float(tf32b(v.y));
                t.z = __uint_as_float(tf32b(v.z));
                t.w = __uint_as_float(tf32b(v.w));
                *(float4*)(&As[r][k4 + q * 4]) = t;
            }
        }
        {
            int r  = tid >> 3;
            int c4 = (tid & 7) * 16;
            const float* wp = W + (size_t)(kc + r) * 128 + c4;
#pragma unroll
            for (int q = 0; q < 4; q++) {
                float4 v = *(const float4*)(wp + q * 4);
                float4 t;
                t.x = __uint_as_float(tf32b(v.x));
                t.y = __uint_as_float(tf32b(v.y));
                t.z = __uint_as_float(tf32b(v.z));
                t.w = __uint_as_float(tf32b(v.w));
                *(float4*)(&Ws[r][c4 + q * 4]) = t;
            }
        }
        __syncthreads();

#pragma unroll
        for (int ks = 0; ks < 4; ks++) {
            int k0 = ks * 8;
            unsigned int af[2][4];
#pragma unroll
            for (int ar = 0; ar < 2; ar++) {
                int rb = wr * 32 + ar * 16;
                af[ar][0] = __float_as_uint(As[rb + gid    ][k0 + tig]);
                af[ar][1] = __float_as_uint(As[rb + gid + 8][k0 + tig]);
                af[ar][2] = __float_as_uint(As[rb + gid    ][k0 + tig + 4]);
                af[ar][3] = __float_as_uint(As[rb + gid + 8][k0 + tig + 4]);
            }
#pragma unroll
            for (int ac = 0; ac < 8; ac++) {
                int cb = wc * 64 + ac * 8;
                unsigned int b0 = __float_as_uint(Ws[k0 + tig    ][cb + gid]);
                unsigned int b1 = __float_as_uint(Ws[k0 + tig + 4][cb + gid]);
                mma_tf32(acc[0][ac], af[0], b0, b1);
                mma_tf32(acc[1][ac], af[1], b0, b1);
            }
        }
        __syncthreads();
    }

#pragma unroll
    for (int ar = 0; ar < 2; ar++) {
        int rb = row0 + wr * 32 + ar * 16;
#pragma unroll
        for (int ac = 0; ac < 8; ac++) {
            int col = wc * 64 + ac * 8 + 2 * tig;
            float b0v = bias ? bias[col]     : 0.f;
            float b1v = bias ? bias[col + 1] : 0.f;
            int r0 = rb + gid, r1 = rb + gid + 8;
            if (r0 < M) {
                float2 v = make_float2(acc[ar][ac][0] + b0v, acc[ar][ac][1] + b1v);
                *(float2*)(C + (size_t)r0 * 128 + col) = v;
            }
            if (r1 < M) {
                float2 v = make_float2(acc[ar][ac][2] + b0v, acc[ar][ac][3] + b1v);
                *(float2*)(C + (size_t)r1 * 128 + col) = v;
            }
        }
    }
}

// ---------------- fused xl/xr GEMM: one A tile, two weight matrices ----------
#define LR_SMF 13312

__global__ void __launch_bounds__(512) k_gemm_lr(const float* __restrict__ A,
                                                 const float* __restrict__ Wlp,
                                                 const float* __restrict__ blp,
                                                 const float* __restrict__ Wrp,
                                                 float* __restrict__ Cl,
                                                 float* __restrict__ Cr, int M) {
    extern __shared__ float smlr[];
    float* As  = smlr;           // [128][36]
    float* Wsl = smlr + 4608;    // [32][136]
    float* Wsr = smlr + 8960;    // [32][136]
    int tid  = threadIdx.x;
    int warp = tid >> 5, lane = tid & 31;
    int gid = lane >> 2, tig = lane & 3;
    int wr = warp & 3, wc = warp >> 2;       // wc 0..3
    int row0 = blockIdx.x * 128;
    const float* Wsrc = (wc < 2) ? Wsl : Wsr;
    int cbase = (wc & 1) * 64;

    float acc[2][8][4];
#pragma unroll
    for (int ar = 0; ar < 2; ar++)
#pragma unroll
        for (int ac = 0; ac < 8; ac++)
#pragma unroll
            for (int q = 0; q < 4; q++) acc[ar][ac][q] = 0.f;

    for (int kc = 0; kc < 128; kc += 32) {
        {
            int r  = tid >> 2;
            int k4 = (tid & 3) * 8;
            bool ok = (row0 + r) < M;
            const float* ap = A + (size_t)(row0 + r) * 128 + kc + k4;
#pragma unroll
            for (int q = 0; q < 2; q++) {
                float4 v = ok ? *(const float4*)(ap + q * 4)
                              : make_float4(0.f, 0.f, 0.f, 0.f);
                float4 t;
                t.x = __uint_as_float(tf32b(v.x));
                t.y = __uint_as_float(tf32b(v.y));
                t.z = __uint_as_float(tf32b(v.z));
                t.w = __uint_as_float(tf32b(v.w));
                *(float4*)(&As[r * 36 + k4 + q * 4]) = t;
            }
        }
        {
            int r  = tid >> 4;
            int c8 = (tid & 15) * 8;
            const float* wlp_ = Wlp + (size_t)(kc + r) * 128 + c8;
            const float* wrp_ = Wrp + (size_t)(kc + r) * 128 + c8;
#pragma unroll
            for (int q = 0; q < 2; q++) {
                float4 v = *(const float4*)(wlp_ + q * 4);
                float4 t;
                t.x = __uint_as_float(tf32b(v.x));
                t.y = __uint_as_float(tf32b(v.y));
                t.z = __uint_as_float(tf32b(v.z));
                t.w = __uint_as_float(tf32b(v.w));
                *(float4*)(&Wsl[r * 136 + c8 + q * 4]) = t;
                float4 u = *(const float4*)(wrp_ + q * 4);
                float4 s;
                s.x = __uint_as_float(tf32b(u.x));
                s.y = __uint_as_float(tf32b(u.y));
                s.z = __uint_as_float(tf32b(u.z));
                s.w = __uint_as_float(tf32b(u.w));
                *(float4*)(&Wsr[r * 136 + c8 + q * 4]) = s;
            }
        }
        __syncthreads();

#pragma unroll
        for (int ks = 0; ks < 4; ks++) {
            int k0 = ks * 8;
            unsigned int af[2][4];
#pragma unroll
            for (int ar = 0; ar < 2; ar++) {
                int rb = wr * 32 + ar * 16;
                af[ar][0] = __float_as_uint(As[(rb + gid    ) * 36 + k0 + tig]);
                af[ar][1] = __float_as_uint(As[(rb + gid + 8) * 36 + k0 + tig]);
                af[ar][2] = __float_as_uint(As[(rb + gid    ) * 36 + k0 + tig + 4]);
                af[ar][3] = __float_as_uint(As[(rb + gid + 8) * 36 + k0 + tig + 4]);
            }
#pragma unroll
            for (int ac = 0; ac < 8; ac++) {
                int cb = cbase + ac * 8;
                unsigned int b0 = __float_as_uint(Wsrc[(k0 + tig    ) * 136 + cb + gid]);
                unsigned int b1 = __float_as_uint(Wsrc[(k0 + tig + 4) * 136 + cb + gid]);
                mma_tf32(acc[0][ac], af[0], b0, b1);
                mma_tf32(acc[1][ac], af[1], b0, b1);
            }
        }
        __syncthreads();
    }

    float* Cdst = (wc < 2) ? Cl : Cr;
    const float* bp = (wc < 2) ? blp : (const float*)0;
#pragma unroll
    for (int ar = 0; ar < 2; ar++) {
        int rb = row0 + wr * 32 + ar * 16;
#pragma unroll
        for (int ac = 0; ac < 8; ac++) {
            int col = cbase + ac * 8 + 2 * tig;
            float b0v = bp ? bp[col]     : 0.f;
            float b1v = bp ? bp[col + 1] : 0.f;
            int r0 = rb + gid, r1 = rb + gid + 8;
            if (r0 < M) {
                float2 v = make_float2(acc[ar][ac][0] + b0v, acc[ar][ac][1] + b1v);
                *(float2*)(Cdst + (size_t)r0 * 128 + col) = v;
            }
            if (r1 < M) {
                float2 v = make_float2(acc[ar][ac][2] + b0v, acc[ar][ac][3] + b1v);
                *(float2*)(Cdst + (size_t)r1 * 128 + col) = v;
            }
        }
    }
}

// ---------------- phase A: edge GEMM + score in CSR (dst-sorted) order --------
// Block covers CSR positions [e0, e0+128). Consecutive rows share dst -> xr
// gathers become L1 hits. ez and src are written at the CSR position so
// phase B reads them sequentially.
__global__ void __launch_bounds__(256, 2) k_escore(const float* __restrict__ ea,
                                                   const float* __restrict__ We,
                                                   const float* __restrict__ att,
                                                   int E, int T) {
    __shared__ float As[32][128];    // [k][edge-row]
    __shared__ float Ws[32][128];    // [k][col]
    __shared__ int   ssrc[128], sdst[128];
    __shared__ float sp[128][17];    // per-row logit partials

    int tid = threadIdx.x;
    int e0  = blockIdx.x * 128;
    int ty = tid >> 4, tx = tid & 15;

    {
        const float4* src = (const float4*)We;
        float4* dstp = (float4*)&Ws[0][0];
#pragma unroll
        for (int q = 0; q < 4; q++) dstp[tid + q * 256] = src[tid + q * 256];
    }
    if (tid < 128) {
        int p_ = e0 + tid;
        if (p_ < T) {
            int eid = g_eid[p_];
            int s, d;
            if (eid < E) { s = g_src[eid]; d = g_dst[eid]; }
            else         { s = d = eid - E; }
            ssrc[tid] = s; sdst[tid] = d;
            g_srcs[p_] = s;
        } else {
            ssrc[tid] = sdst[tid] = 0;
        }
    }
    {
        int arow = tid >> 1;
        int kb   = (tid & 1) * 16;
        int p_   = e0 + arow;
        const float* rowp = (const float*)0;
        if (p_ < T) {
            int eid = g_eid[p_];
            rowp = (eid < E) ? (ea + (size_t)eid * 32)
                             : (g_loop + (size_t)(eid - E) * 32);
        }
#pragma unroll
        for (int q = 0; q < 4; q++) {
            float4 v = rowp ? *(const float4*)(rowp + kb + q * 4)
                            : make_float4(0.f, 0.f, 0.f, 0.f);
            As[kb + q * 4 + 0][arow] = v.x;
            As[kb + q * 4 + 1][arow] = v.y;
            As[kb + q * 4 + 2][arow] = v.z;
            As[kb + q * 4 + 3][arow] = v.w;
        }
    }
    __syncthreads();

    unsigned long long acc2[8][4];
#pragma unroll
    for (int i = 0; i < 8; i++)
#pragma unroll
        for (int j = 0; j < 4; j++) acc2[i][j] = 0ULL;

#pragma unroll
    for (int k = 0; k < 32; k++) {
        float a[8];
        unsigned long long b2[4];
        *(float4*)(a)     = *(float4*)(&As[k][ty * 8]);
        *(float4*)(a + 4) = *(float4*)(&As[k][ty * 8 + 4]);
        const unsigned long long* wp = (const unsigned long long*)(&Ws[k][tx * 8]);
        b2[0] = wp[0]; b2[1] = wp[1]; b2[2] = wp[2]; b2[3] = wp[3];
#pragma unroll
        for (int i = 0; i < 8; i++) {
            unsigned long long pa = pk2(a[i], a[i]);
#pragma unroll
            for (int j = 0; j < 4; j++) fma2(acc2[i][j], pa, b2[j]);
        }
    }

    float4 at0 = *(const float4*)(att + tx * 8);
    float4 at1 = *(const float4*)(att + tx * 8 + 4);
#pragma unroll
    for (int i = 0; i < 8; i++) {
        int r = ty * 8 + i;
        int s = ssrc[r], d = sdst[r];
        const float* xlp = g_xl + (size_t)s * HID + tx * 8;
        const float* xrp = g_xr + (size_t)d * HID + tx * 8;
        float4 xl0 = *(const float4*)(xlp);
        float4 xl1 = *(const float4*)(xlp + 4);
        float4 xr0 = *(const float4*)(xrp);
        float4 xr1 = *(const float4*)(xrp + 4);
        float2 v0 = up2(acc2[i][0]);
        float2 v1 = up2(acc2[i][1]);
        float2 v2 = up2(acc2[i][2]);
        float2 v3 = up2(acc2[i][3]);
        float p = lk(xl0.x + xr0.x + v0.x) * at0.x
                + lk(xl0.y + xr0.y + v0.y) * at0.y
                + lk(xl0.z + xr0.z + v1.x) * at0.z
                + lk(xl0.w + xr0.w + v1.y) * at0.w
                + lk(xl1.x + xr1.x + v2.x) * at1.x
                + lk(xl1.y + xr1.y + v2.y) * at1.y
                + lk(xl1.z + xr1.z + v3.x) * at1.z
                + lk(xl1.w + xr1.w + v3.y) * at1.w;
        sp[r][tx] = p;
    }
    __syncthreads();

    if (tid < 128) {
        float sum = 0.f;
#pragma unroll
        for (int j = 0; j < 16; j++) sum += sp[tid][j];
        int p_ = e0 + tid;
        if (p_ < T) g_ez[p_] = __expf(sum);
    }
}

// ---------------- phase B: CSR aggregation + norm + bias + silu ----------------
// ez and src are CSR-positional -> sequential/broadcast loads; only xl is a gather.
__global__ void __launch_bounds__(256) k_aggr(const float* __restrict__ bo,
                                              float* __restrict__ out,
                                              int E, int N) {
    int w = (blockIdx.x * blockDim.x + threadIdx.x) >> 5;
    int lane = threadIdx.x & 31;
    if (w >= N) return;
    int lo = g_off[w], hi = g_off[w + 1];
    int c = lane * 4;
    float ax = 0.f, ay = 0.f, az = 0.f, aw = 0.f, den = 0.f;
    for (int p = lo; p < hi; p++) {
        float ez = g_ez[p];
        int s = g_srcs[p];
        float4 xl = *(const float4*)(g_xl + (size_t)s * HID + c);
        ax += ez * xl.x; ay += ez * xl.y; az += ez * xl.z; aw += ez * xl.w;
        den += ez;
    }
    float inv = 1.0f / den;
    float4 b = *(const float4*)(bo + c);
    float vx = ax * inv + b.x;
    float vy = ay * inv + b.y;
    float vz = az * inv + b.z;
    float vw = aw * inv + b.w;
    float4 o;
    o.x = vx / (1.0f + __expf(-vx));
    o.y = vy / (1.0f + __expf(-vy));
    o.z = vz / (1.0f + __expf(-vz));
    o.w = vw / (1.0f + __expf(-vw));
    *(float4*)(out + (size_t)w * HID + c) = o;
}

// ---------------- host orchestration ----------------
extern "C" void kernel_launch(void* const* d_in, const int* in_sizes, int n_in,
                              void* d_out, int out_size) {
    const float* x    = (const float*)d_in[0];
    const void*  eidx = d_in[1];
    const float* ea   = (const float*)d_in[2];
    const float* W_emb = (const float*)d_in[3];
    const float* b_emb = (const float*)d_in[4];
    const float* Wl[2]  = {(const float*)d_in[5],  (const float*)d_in[11]};
    const float* bl[2]  = {(const float*)d_in[6],  (const float*)d_in[12]};
    const float* Wr[2]  = {(const float*)d_in[7],  (const float*)d_in[13]};
    const float* We[2]  = {(const float*)d_in[8],  (const float*)d_in[14]};
    const float* att[2] = {(const float*)d_in[9],  (const float*)d_in[15]};
    const float* bo[2]  = {(const float*)d_in[10], (const float*)d_in[16]};

    int N = in_sizes[0] / HID;
    int E = in_sizes[2] / 32;
    int T = E + N;

    float *p_h, *p_xl, *p_xr;
    cudaGetSymbolAddress((void**)&p_h,  g_h);
    cudaGetSymbolAddress((void**)&p_xl, g_xl);
    cudaGetSymbolAddress((void**)&p_xr, g_xr);

    int gb_n = (N + 127) / 128;
    int nblk = (N + 255) / 256;
    int wb_n = (N * 32 + 255) / 256;

    int lr_smem = LR_SMF * 4;   // 53 KB
    cudaFuncSetAttribute(k_gemm_lr, cudaFuncAttributeMaxDynamicSharedMemorySize, lr_smem);

    k_detect<<<1, 1>>>(eidx, E, N);                                   // 1
    k_zero_cnt<<<nblk, 256>>>(N);                                     // 2
    k_prep<<<(E + 255) / 256, 256>>>(eidx, E);                        // 3 (conv+count)
    k_gemm_tc<<<gb_n, 256>>>(x, W_emb, b_emb, p_h, N);                // 4 <- profiled
    k_scan_local<<<nblk, 256>>>(N);                                   // 5
    k_scan_blk<<<1, 256>>>(nblk);                                     // 6
    k_scan_add<<<nblk, 256>>>(N, T);                                  // 7
    k_scatter<<<(T + 255) / 256, 256>>>(E, T);                        // 8
    k_loopcsr<<<wb_n, 256>>>(ea, E, N);                               // 9

    int eb = (T + 127) / 128;
    for (int l = 0; l < 2; l++) {
        k_gemm_lr<<<gb_n, 512, lr_smem>>>(p_h, Wl[l], bl[l], Wr[l], p_xl, p_xr, N);
        k_escore<<<eb, 256>>>(ea, We[l], att[l], E, T);
        float* dst = (l == 0) ? p_h : (float*)d_out;
        k_aggr<<<wb_n, 256>>>(bo[l], dst, E, N);
    }
}

// round 13
// speedup vs baseline: 1.1071x; 1.0076x over previous
#include <cuda_runtime.h>
#include <math.h>

#define HID 128
#define NEG 0.2f
#define MAXN 50000
#define MAXE 800000
#define MAXT (MAXE + MAXN)

// ---------------- static scratch (no allocations allowed) ----------------
__device__ float g_h  [MAXN * HID];
__device__ float g_xl [MAXN * HID];
__device__ float g_xr [MAXN * HID];
__device__ float g_loop[MAXN * 32];
__device__ float g_ez  [MAXT];     // indexed by CSR position
__device__ int   g_srcs[MAXT];     // src per CSR position
__device__ int   g_src[MAXE];
__device__ int   g_dst[MAXE];
__device__ int   g_cnt[MAXN];
__device__ int   g_scanA[MAXN];
__device__ int   g_blksum[256];
__device__ int   g_blkoff[256];
__device__ int   g_off[MAXN + 1];
__device__ int   g_cursor[MAXN];
__device__ int   g_eid[MAXT];
__device__ int   g_is64;
// composed layer-1 weights (emb folded in)
__device__ float g_wlc[128 * 128];
__device__ float g_wrc[128 * 128];
__device__ float g_blc[128];
__device__ float g_brc[128];

// ---------------- small helpers ----------------
__device__ __forceinline__ float lk(float x) { return x > 0.0f ? x : NEG * x; }

__device__ __forceinline__ unsigned long long pk2(float x, float y) {
    unsigned long long r;
    asm("mov.b64 %0, {%1, %2};" : "=l"(r) : "f"(x), "f"(y));
    return r;
}
__device__ __forceinline__ void fma2(unsigned long long& d,
                                     unsigned long long a, unsigned long long b) {
    asm("fma.rn.f32x2 %0, %1, %2, %0;" : "+l"(d) : "l"(a), "l"(b));
}
__device__ __forceinline__ float2 up2(unsigned long long v) {
    float2 r;
    asm("mov.b64 {%0, %1}, %2;" : "=f"(r.x), "=f"(r.y) : "l"(v));
    return r;
}
__device__ __forceinline__ unsigned int tf32b(float x) {
    unsigned int r;
    asm("cvt.rna.tf32.f32 %0, %1;" : "=r"(r) : "f"(x));
    return r;
}
__device__ __forceinline__ void mma_tf32(float* d, const unsigned int* a,
                                         unsigned int b0, unsigned int b1) {
    asm("mma.sync.aligned.m16n8k8.row.col.f32.tf32.tf32.f32 "
        "{%0,%1,%2,%3}, {%4,%5,%6,%7}, {%8,%9}, {%0,%1,%2,%3};"
        : "+f"(d[0]), "+f"(d[1]), "+f"(d[2]), "+f"(d[3])
        : "r"(a[0]), "r"(a[1]), "r"(a[2]), "r"(a[3]), "r"(b0), "r"(b1));
}
__device__ __forceinline__ float4 cvt4(float4 v) {
    float4 t;
    t.x = __uint_as_float(tf32b(v.x));
    t.y = __uint_as_float(tf32b(v.y));
    t.z = __uint_as_float(tf32b(v.z));
    t.w = __uint_as_float(tf32b(v.w));
    return t;
}

// ---------------- dtype detection + index conversion (+count fused) ----------
__global__ void k_detect(const void* __restrict__ idx, int E, int N) {
    if (threadIdx.x == 0 && blockIdx.x == 0) {
        const long long* p = (const long long*)idx;
        int ok = 1;
        int cnt = 64;
        if (2 * E < 64) cnt = 2 * E;
        for (int i = 0; i < cnt; i++) {
            long long v = p[i];
            if (v < 0 || v >= (long long)N) { ok = 0; break; }
        }
        g_is64 = ok;
    }
}

__global__ void k_zero_cnt(int N) {
    int i = blockIdx.x * blockDim.x + threadIdx.x;
    if (i < N) g_cnt[i] = 0;
}

__global__ void k_prep(const void* __restrict__ idx, int E) {
    int e = blockIdx.x * blockDim.x + threadIdx.x;
    if (e >= E) return;
    int s, d;
    if (g_is64) {
        s = (int)((const long long*)idx)[e];
        d = (int)((const long long*)idx)[E + e];
    } else {
        s = ((const int*)idx)[e];
        d = ((const int*)idx)[E + e];
    }
    g_src[e] = s;
    g_dst[e] = d;
    atomicAdd(&g_cnt[d], 1);
}

// ---------------- CSR build: scan -> scatter ----------------
__global__ void k_scan_local(int N) {
    __shared__ int s[256];
    int b = blockIdx.x, t = threadIdx.x, i = b * 256 + t;
    int v = (i < N) ? g_cnt[i] + 1 : 0;
    s[t] = v;
    __syncthreads();
    for (int o = 1; o < 256; o <<= 1) {
        int x = (t >= o) ? s[t - o] : 0;
        __syncthreads();
        s[t] += x;
        __syncthreads();
    }
    if (i < N) g_scanA[i] = s[t];
    if (t == 255) g_blksum[b] = s[255];
}
__global__ void k_scan_blk(int nblk) {
    __shared__ int s[256];
    int t = threadIdx.x;
    int v = (t < nblk) ? g_blksum[t] : 0;
    s[t] = v;
    __syncthreads();
    for (int o = 1; o < 256; o <<= 1) {
        int x = (t >= o) ? s[t - o] : 0;
        __syncthreads();
        s[t] += x;
        __syncthreads();
    }
    g_blkoff[t] = s[t] - v;   // exclusive
}
__global__ void k_scan_add(int N, int T) {
    int i = blockIdx.x * blockDim.x + threadIdx.x;
    if (i < N) {
        int v = g_cnt[i] + 1;
        int off = g_scanA[i] - v + g_blkoff[i >> 8];
        g_off[i] = off;
        g_cursor[i] = off;
    }
    if (i == 0) g_off[N] = T;
}
__global__ void k_scatter(int E, int T) {
    int e = blockIdx.x * blockDim.x + threadIdx.x;
    if (e >= T) return;
    int d = (e < E) ? g_dst[e] : e - E;
    int pos = atomicAdd(&g_cursor[d], 1);
    g_eid[pos] = e;
}

// ---------------- self-loop attr from CSR (atomic-free) ----------------
__global__ void __launch_bounds__(256) k_loopcsr(const float* __restrict__ ea,
                                                 int E, int N) {
    int w = (blockIdx.x * blockDim.x + threadIdx.x) >> 5;
    int lane = threadIdx.x & 31;
    if (w >= N) return;
    int lo = g_off[w], hi = g_off[w + 1];
    float sum = 0.f;
    int cnt = 0;
    for (int p = lo; p < hi; p++) {
        int eid = g_eid[p];
        if (eid < E) { sum += ea[(size_t)eid * 32 + lane]; cnt++; }
    }
    g_loop[(size_t)w * 32 + lane] = sum / fmaxf((float)cnt, 1.f);
}

// ---------------- tf32 tensor-core GEMM (used for weight composition) --------
__global__ void __launch_bounds__(256) k_gemm_tc(const float* __restrict__ A,
                                                 const float* __restrict__ W,
                                                 const float* __restrict__ bias,
                                                 float* __restrict__ C, int M) {
    __shared__ float As[128][36];
    __shared__ float Ws[32][136];
    int tid  = threadIdx.x;
    int warp = tid >> 5, lane = tid & 31;
    int gid = lane >> 2, tig = lane & 3;
    int wr = warp & 3, wc = warp >> 2;
    int row0 = blockIdx.x * 128;

    float acc[2][8][4];
#pragma unroll
    for (int ar = 0; ar < 2; ar++)
#pragma unroll
        for (int ac = 0; ac < 8; ac++)
#pragma unroll
            for (int q = 0; q < 4; q++) acc[ar][ac][q] = 0.f;

    for (int kc = 0; kc < 128; kc += 32) {
        {
            int r  = tid >> 1;
            int k4 = (tid & 1) * 16;
            bool ok = (row0 + r) < M;
            const float* ap = A + (size_t)(row0 + r) * 128 + kc + k4;
#pragma unroll
            for (int q = 0; q < 4; q++) {
                float4 v = ok ? *(const float4*)(ap + q * 4)
                              : make_float4(0.f, 0.f, 0.f, 0.f);
                *(float4*)(&As[r][k4 + q * 4]) = cvt4(v);
            }
        }
        {
            int r  = tid >> 3;
            int c4 = (tid & 7) * 16;
            const float* wp = W + (size_t)(kc + r) * 128 + c4;
#pragma unroll
            for (int q = 0; q < 4; q++) {
                float4 v = *(const float4*)(wp + q * 4);
                *(float4*)(&Ws[r][c4 + q * 4]) = cvt4(v);
            }
        }
        __syncthreads();

#pragma unroll
        for (int ks = 0; ks < 4; ks++) {
            int k0 = ks * 8;
            unsigned int af[2][4];
#pragma unroll
            for (int ar = 0; ar < 2; ar++) {
                int rb = wr * 32 + ar * 16;
                af[ar][0] = __float_as_uint(As[rb + gid    ][k0 + tig]);
                af[ar][1] = __float_as_uint(As[rb + gid + 8][k0 + tig]);
                af[ar][2] = __float_as_uint(As[rb + gid    ][k0 + tig + 4]);
                af[ar][3] = __float_as_uint(As[rb + gid + 8][k0 + tig + 4]);
            }
#pragma unroll
            for (int ac = 0; ac < 8; ac++) {
                int cb = wc * 64 + ac * 8;
                unsigned int b0 = __float_as_uint(Ws[k0 + tig    ][cb + gid]);
                unsigned int b1 = __float_as_uint(Ws[k0 + tig + 4][cb + gid]);
                mma_tf32(acc[0][ac], af[0], b0, b1);
                mma_tf32(acc[1][ac], af[1], b0, b1);
            }
        }
        __syncthreads();
    }

#pragma unroll
    for (int ar = 0; ar < 2; ar++) {
        int rb = row0 + wr * 32 + ar * 16;
#pragma unroll
        for (int ac = 0; ac < 8; ac++) {
            int col = wc * 64 + ac * 8 + 2 * tig;
            float b0v = bias ? bias[col]     : 0.f;
            float b1v = bias ? bias[col + 1] : 0.f;
            int r0 = rb + gid, r1 = rb + gid + 8;
            if (r0 < M) {
                float2 v = make_float2(acc[ar][ac][0] + b0v, acc[ar][ac][1] + b1v);
                *(float2*)(C + (size_t)r0 * 128 + col) = v;
            }
            if (r1 < M) {
                float2 v = make_float2(acc[ar][ac][2] + b0v, acc[ar][ac][3] + b1v);
                *(float2*)(C + (size_t)r1 * 128 + col) = v;
            }
        }
    }
}

// ---------------- bias composition: blc = b_emb@Wl1 + bl1, brc = b_emb@Wr1 ----
__global__ void k_biascomp(const float* __restrict__ b_emb,
                           const float* __restrict__ Wl1,
                           const float* __restrict__ bl1,
                           const float* __restrict__ Wr1) {
    int c = threadIdx.x;   // 0..127
    const float* W = (blockIdx.x == 0) ? Wl1 : Wr1;
    float s = (blockIdx.x == 0) ? bl1[c] : 0.f;
    for (int k = 0; k < 128; k++) s += b_emb[k] * W[k * 128 + c];
    if (blockIdx.x == 0) g_blc[c] = s;
    else                 g_brc[c] = s;
}

// ---------------- fused xl/xr GEMM, software-pipelined K-chunks --------------
#define LR_SMF 13312

__global__ void __launch_bounds__(512) k_gemm_lr(const float* __restrict__ A,
                                                 const float* __restrict__ Wlp,
                                                 const float* __restrict__ blp,
                                                 const float* __restrict__ Wrp,
                                                 const float* __restrict__ brp,
                                                 float* __restrict__ Cl,
                                                 float* __restrict__ Cr, int M) {
    extern __shared__ float smlr[];
    float* As  = smlr;           // [128][36]
    float* Wsl = smlr + 4608;    // [32][136]
    float* Wsr = smlr + 8960;    // [32][136]
    int tid  = threadIdx.x;
    int warp = tid >> 5, lane = tid & 31;
    int gid = lane >> 2, tig = lane & 3;
    int wr = warp & 3, wc = warp >> 2;       // wc 0..3
    int row0 = blockIdx.x * 128;
    const float* Wsrc = (wc < 2) ? Wsl : Wsr;
    int cbase = (wc & 1) * 64;

    int rA  = tid >> 2, k4A = (tid & 3) * 8;
    int rW  = tid >> 4, c8W = (tid & 15) * 8;
    bool okA = (row0 + rA) < M;
    const float* apB = A   + (size_t)(row0 + rA) * 128 + k4A;
    const float* wlB = Wlp + (size_t)rW * 128 + c8W;
    const float* wrB = Wrp + (size_t)rW * 128 + c8W;

    float acc[2][8][4];
#pragma unroll
    for (int ar = 0; ar < 2; ar++)
#pragma unroll
        for (int ac = 0; ac < 8; ac++)
#pragma unroll
            for (int q = 0; q < 4; q++) acc[ar][ac][q] = 0.f;

    float4 pa0, pa1, pl0, pl1, pr0, pr1;
    pa0 = okA ? *(const float4*)(apB)     : make_float4(0.f, 0.f, 0.f, 0.f);
    pa1 = okA ? *(const float4*)(apB + 4) : make_float4(0.f, 0.f, 0.f, 0.f);
    pl0 = *(const float4*)(wlB);
    pl1 = *(const float4*)(wlB + 4);
    pr0 = *(const float4*)(wrB);
    pr1 = *(const float4*)(wrB + 4);

#pragma unroll
    for (int kc4 = 0; kc4 < 4; kc4++) {
        *(float4*)(&As[rA * 36 + k4A])       = cvt4(pa0);
        *(float4*)(&As[rA * 36 + k4A + 4])   = cvt4(pa1);
        *(float4*)(&Wsl[rW * 136 + c8W])     = cvt4(pl0);
        *(float4*)(&Wsl[rW * 136 + c8W + 4]) = cvt4(pl1);
        *(float4*)(&Wsr[rW * 136 + c8W])     = cvt4(pr0);
        *(float4*)(&Wsr[rW * 136 + c8W + 4]) = cvt4(pr1);
        __syncthreads();

        if (kc4 < 3) {
            int kc = (kc4 + 1) * 32;
            pa0 = okA ? *(const float4*)(apB + kc)     : make_float4(0.f, 0.f, 0.f, 0.f);
            pa1 = okA ? *(const float4*)(apB + kc + 4) : make_float4(0.f, 0.f, 0.f, 0.f);
            pl0 = *(const float4*)(wlB + (size_t)kc * 128);
            pl1 = *(const float4*)(wlB + (size_t)kc * 128 + 4);
            pr0 = *(const float4*)(wrB + (size_t)kc * 128);
            pr1 = *(const float4*)(wrB + (size_t)kc * 128 + 4);
        }

#pragma unroll
        for (int ks = 0; ks < 4; ks++) {
            int k0 = ks * 8;
            unsigned int af[2][4];
#pragma unroll
            for (int ar = 0; ar < 2; ar++) {
                int rb = wr * 32 + ar * 16;
                af[ar][0] = __float_as_uint(As[(rb + gid    ) * 36 + k0 + tig]);
                af[ar][1] = __float_as_uint(As[(rb + gid + 8) * 36 + k0 + tig]);
                af[ar][2] = __float_as_uint(As[(rb + gid    ) * 36 + k0 + tig + 4]);
                af[ar][3] = __float_as_uint(As[(rb + gid + 8) * 36 + k0 + tig + 4]);
            }
#pragma unroll
            for (int ac = 0; ac < 8; ac++) {
                int cb = cbase + ac * 8;
                unsigned int b0 = __float_as_uint(Wsrc[(k0 + tig    ) * 136 + cb + gid]);
                unsigned int b1 = __float_as_uint(Wsrc[(k0 + tig + 4) * 136 + cb + gid]);
                mma_tf32(acc[0][ac], af[0], b0, b1);
                mma_tf32(acc[1][ac], af[1], b0, b1);
            }
        }
        __syncthreads();
    }

    float* Cdst = (wc < 2) ? Cl : Cr;
    const float* bp = (wc < 2) ? blp : brp;
#pragma unroll
    for (int ar = 0; ar < 2; ar++) {
        int rb = row0 + wr * 32 + ar * 16;
#pragma unroll
        for (int ac = 0; ac < 8; ac++) {
            int col = cbase + ac * 8 + 2 * tig;
            float b0v = bp ? bp[col]     : 0.f;
            float b1v = bp ? bp[col + 1] : 0.f;
            int r0 = rb + gid, r1 = rb + gid + 8;
            if (r0 < M) {
                float2 v = make_float2(acc[ar][ac][0] + b0v, acc[ar][ac][1] + b1v);
                *(float2*)(Cdst + (size_t)r0 * 128 + col) = v;
            }
            if (r1 < M) {
                float2 v = make_float2(acc[ar][ac][2] + b0v, acc[ar][ac][3] + b1v);
                *(float2*)(Cdst + (size_t)r1 * 128 + col) = v;
            }
        }
    }
}

// ---------------- phase A: edge GEMM + score in CSR (dst-sorted) order --------
__global__ void __launch_bounds__(256, 2) k_escore(const float* __restrict__ ea,
                                                   const float* __restrict__ We,
                                                   const float* __restrict__ att,
                                                   int E, int T) {
    __shared__ float As[32][128];    // [k][edge-row]
    __shared__ float Ws[32][128];    // [k][col]
    __shared__ int   ssrc[128], sdst[128];
    __shared__ float sp[128][17];    // per-row logit partials

    int tid = threadIdx.x;
    int e0  = blockIdx.x * 128;
    int ty = tid >> 4, tx = tid & 15;

    {
        const float4* src = (const float4*)We;
        float4* dstp = (float4*)&Ws[0][0];
#pragma unroll
        for (int q = 0; q < 4; q++) dstp[tid + q * 256] = src[tid + q * 256];
    }
    if (tid < 128) {
        int p_ = e0 + tid;
        if (p_ < T) {
            int eid = g_eid[p_];
            int s, d;
            if (eid < E) { s = g_src[eid]; d = g_dst[eid]; }
            else         { s = d = eid - E; }
            ssrc[tid] = s; sdst[tid] = d;
            g_srcs[p_] = s;
        } else {
            ssrc[tid] = sdst[tid] = 0;
        }
    }
    {
        int arow = tid >> 1;
        int kb   = (tid & 1) * 16;
        int p_   = e0 + arow;
        const float* rowp = (const float*)0;
        if (p_ < T) {
            int eid = g_eid[p_];
            rowp = (eid < E) ? (ea + (size_t)eid * 32)
                             : (g_loop + (size_t)(eid - E) * 32);
        }
#pragma unroll
        for (int q = 0; q < 4; q++) {
            float4 v = rowp ? *(const float4*)(rowp + kb + q * 4)
                            : make_float4(0.f, 0.f, 0.f, 0.f);
            As[kb + q * 4 + 0][arow] = v.x;
            As[kb + q * 4 + 1][arow] = v.y;
            As[kb + q * 4 + 2][arow] = v.z;
            As[kb + q * 4 + 3][arow] = v.w;
        }
    }
    __syncthreads();

    unsigned long long acc2[8][4];
#pragma unroll
    for (int i = 0; i < 8; i++)
#pragma unroll
        for (int j = 0; j < 4; j++) acc2[i][j] = 0ULL;

#pragma unroll
    for (int k = 0; k < 32; k++) {
        float a[8];
        unsigned long long b2[4];
        *(float4*)(a)     = *(float4*)(&As[k][ty * 8]);
        *(float4*)(a + 4) = *(float4*)(&As[k][ty * 8 + 4]);
        const unsigned long long* wp = (const unsigned long long*)(&Ws[k][tx * 8]);
        b2[0] = wp[0]; b2[1] = wp[1]; b2[2] = wp[2]; b2[3] = wp[3];
#pragma unroll
        for (int i = 0; i < 8; i++) {
            unsigned long long pa = pk2(a[i], a[i]);
#pragma unroll
            for (int j = 0; j < 4; j++) fma2(acc2[i][j], pa, b2[j]);
        }
    }

    float4 at0 = *(const float4*)(att + tx * 8);
    float4 at1 = *(const float4*)(att + tx * 8 + 4);
#pragma unroll
    for (int i = 0; i < 8; i++) {
        int r = ty * 8 + i;
        int s = ssrc[r], d = sdst[r];
        const float* xlp = g_xl + (size_t)s * HID + tx * 8;
        const float* xrp = g_xr + (size_t)d * HID + tx * 8;
        float4 xl0 = *(const float4*)(xlp);
        float4 xl1 = *(const float4*)(xlp + 4);
        float4 xr0 = *(const float4*)(xrp);
        float4 xr1 = *(const float4*)(xrp + 4);
        float2 v0 = up2(acc2[i][0]);
        float2 v1 = up2(acc2[i][1]);
        float2 v2 = up2(acc2[i][2]);
        float2 v3 = up2(acc2[i][3]);
        float p = lk(xl0.x + xr0.x + v0.x) * at0.x
                + lk(xl0.y + xr0.y + v0.y) * at0.y
                + lk(xl0.z + xr0.z + v1.x) * at0.z
                + lk(xl0.w + xr0.w + v1.y) * at0.w
                + lk(xl1.x + xr1.x + v2.x) * at1.x
                + lk(xl1.y + xr1.y + v2.y) * at1.y
                + lk(xl1.z + xr1.z + v3.x) * at1.z
                + lk(xl1.w + xr1.w + v3.y) * at1.w;
        sp[r][tx] = p;
    }
    __syncthreads();

    if (tid < 128) {
        float sum = 0.f;
#pragma unroll
        for (int j = 0; j < 16; j++) sum += sp[tid][j];
        int p_ = e0 + tid;
        if (p_ < T) g_ez[p_] = __expf(sum);
    }
}

// ---------------- phase B: CSR aggregation + norm + bias + silu ----------------
__global__ void __launch_bounds__(256) k_aggr(const float* __restrict__ bo,
                                              float* __restrict__ out,
                                              int E, int N) {
    int w = (blockIdx.x * blockDim.x + threadIdx.x) >> 5;
    int lane = threadIdx.x & 31;
    if (w >= N) return;
    int lo = g_off[w], hi = g_off[w + 1];
    int c = lane * 4;
    float ax = 0.f, ay = 0.f, az = 0.f, aw = 0.f, den = 0.f;
    for (int p = lo; p < hi; p++) {
        float ez = g_ez[p];
        int s = g_srcs[p];
        float4 xl = *(const float4*)(g_xl + (size_t)s * HID + c);
        ax += ez * xl.x; ay += ez * xl.y; az += ez * xl.z; aw += ez * xl.w;
        den += ez;
    }
    float inv = 1.0f / den;
    float4 b = *(const float4*)(bo + c);
    float vx = ax * inv + b.x;
    float vy = ay * inv + b.y;
    float vz = az * inv + b.z;
    float vw = aw * inv + b.w;
    float4 o;
    o.x = vx / (1.0f + __expf(-vx));
    o.y = vy / (1.0f + __expf(-vy));
    o.z = vz / (1.0f + __expf(-vz));
    o.w = vw / (1.0f + __expf(-vw));
    *(float4*)(out + (size_t)w * HID + c) = o;
}

// ---------------- host orchestration ----------------
extern "C" void kernel_launch(void* const* d_in, const int* in_sizes, int n_in,
                              void* d_out, int out_size) {
    const float* x    = (const float*)d_in[0];
    const void*  eidx = d_in[1];
    const float* ea   = (const float*)d_in[2];
    const float* W_emb = (const float*)d_in[3];
    const float* b_emb = (const float*)d_in[4];
    const float* Wl[2]  = {(const float*)d_in[5],  (const float*)d_in[11]};
    const float* bl[2]  = {(const float*)d_in[6],  (const float*)d_in[12]};
    const float* Wr[2]  = {(const float*)d_in[7],  (const float*)d_in[13]};
    const float* We[2]  = {(const float*)d_in[8],  (const float*)d_in[14]};
    const float* att[2] = {(const float*)d_in[9],  (const float*)d_in[15]};
    const float* bo[2]  = {(const float*)d_in[10], (const float*)d_in[16]};

    int N = in_sizes[0] / HID;
    int E = in_sizes[2] / 32;
    int T = E + N;

    float *p_h, *p_xl, *p_xr, *p_wlc, *p_wrc, *p_blc, *p_brc;
    cudaGetSymbolAddress((void**)&p_h,   g_h);
    cudaGetSymbolAddress((void**)&p_xl,  g_xl);
    cudaGetSymbolAddress((void**)&p_xr,  g_xr);
    cudaGetSymbolAddress((void**)&p_wlc, g_wlc);
    cudaGetSymbolAddress((void**)&p_wrc, g_wrc);
    cudaGetSymbolAddress((void**)&p_blc, g_blc);
    cudaGetSymbolAddress((void**)&p_brc, g_brc);

    int gb_n = (N + 127) / 128;
    int nblk = (N + 255) / 256;
    int wb_n = (N * 32 + 255) / 256;

    int lr_smem = LR_SMF * 4;   // 53 KB
    cudaFuncSetAttribute(k_gemm_lr, cudaFuncAttributeMaxDynamicSharedMemorySize, lr_smem);

    // weight composition: fold emb GEMM into layer-1 transforms
    k_gemm_tc<<<1, 256>>>(W_emb, Wl[0], nullptr, p_wlc, 128);          // 1
    k_gemm_tc<<<1, 256>>>(W_emb, Wr[0], nullptr, p_wrc, 128);          // 2
    k_biascomp<<<2, 128>>>(b_emb, Wl[0], bl[0], Wr[0]);                // 3
    // layer-1 xl/xr straight from x (profiled launch position)
    k_gemm_lr<<<gb_n, 512, lr_smem>>>(x, p_wlc, p_blc, p_wrc, p_brc,
                                      p_xl, p_xr, N);                  // 4 <- profiled
    // CSR build
    k_detect<<<1, 1>>>(eidx, E, N);                                    // 5
    k_zero_cnt<<<nblk, 256>>>(N);                                      // 6
    k_prep<<<(E + 255) / 256, 256>>>(eidx, E);                         // 7
    k_scan_local<<<nblk, 256>>>(N);                                    // 8
    k_scan_blk<<<1, 256>>>(nblk);                                      // 9
    k_scan_add<<<nblk, 256>>>(N, T);                                   // 10
    k_scatter<<<(T + 255) / 256, 256>>>(E, T);                         // 11
    k_loopcsr<<<wb_n, 256>>>(ea, E, N);                                // 12

    int eb = (T + 127) / 128;
    // layer 1
    k_escore<<<eb, 256>>>(ea, We[0], att[0], E, T);                    // 13
    k_aggr<<<wb_n, 256>>>(bo[0], p_h, E, N);                           // 14
    // layer 2
    k_gemm_lr<<<gb_n, 512, lr_smem>>>(p_h, Wl[1], bl[1], Wr[1], nullptr,
                                      p_xl, p_xr, N);                  // 15
    k_escore<<<eb, 256>>>(ea, We[1], att[1], E, T);                    // 16
    k_aggr<<<wb_n, 256>>>(bo[1], (float*)d_out, E, N);                 // 17
}

// round 14
// speedup vs baseline: 1.1495x; 1.0384x over previous
#include <cuda_runtime.h>
#include <math.h>

#define HID 128
#define NEG 0.2f
#define MAXN 50000
#define MAXE 800000
#define MAXT (MAXE + MAXN)

// ---------------- static scratch (no allocations allowed) ----------------
__device__ float g_h  [MAXN * HID];
__device__ float g_xl [MAXN * HID];
__device__ float g_xr [MAXN * HID];
__device__ float g_loop[MAXN * 32];
__device__ float g_ez  [MAXT];     // indexed by CSR position
__device__ int   g_srcs[MAXT];     // src per CSR position
__device__ int   g_src[MAXE];
__device__ int   g_dst[MAXE];
__device__ int   g_cnt[MAXN];
__device__ int   g_scanA[MAXN];
__device__ int   g_blksum[256];
__device__ int   g_blkoff[256];
__device__ int   g_off[MAXN + 1];
__device__ int   g_cursor[MAXN];
__device__ int   g_eid[MAXT];
__device__ int   g_is64;
// composed layer-1 weights (emb folded in)
__device__ float g_wlc[128 * 128];
__device__ float g_wrc[128 * 128];
__device__ float g_blc[128];
__device__ float g_brc[128];

// ---------------- small helpers ----------------
__device__ __forceinline__ float lk(float x) { return x > 0.0f ? x : NEG * x; }

__device__ __forceinline__ unsigned long long pk2(float x, float y) {
    unsigned long long r;
    asm("mov.b64 %0, {%1, %2};" : "=l"(r) : "f"(x), "f"(y));
    return r;
}
__device__ __forceinline__ void fma2(unsigned long long& d,
                                     unsigned long long a, unsigned long long b) {
    asm("fma.rn.f32x2 %0, %1, %2, %0;" : "+l"(d) : "l"(a), "l"(b));
}
__device__ __forceinline__ float2 up2(unsigned long long v) {
    float2 r;
    asm("mov.b64 {%0, %1}, %2;" : "=f"(r.x), "=f"(r.y) : "l"(v));
    return r;
}
__device__ __forceinline__ unsigned int tf32b(float x) {
    unsigned int r;
    asm("cvt.rna.tf32.f32 %0, %1;" : "=r"(r) : "f"(x));
    return r;
}
__device__ __forceinline__ void mma_tf32(float* d, const unsigned int* a,
                                         unsigned int b0, unsigned int b1) {
    asm("mma.sync.aligned.m16n8k8.row.col.f32.tf32.tf32.f32 "
        "{%0,%1,%2,%3}, {%4,%5,%6,%7}, {%8,%9}, {%0,%1,%2,%3};"
        : "+f"(d[0]), "+f"(d[1]), "+f"(d[2]), "+f"(d[3])
        : "r"(a[0]), "r"(a[1]), "r"(a[2]), "r"(a[3]), "r"(b0), "r"(b1));
}
__device__ __forceinline__ float4 cvt4(float4 v) {
    float4 t;
    t.x = __uint_as_float(tf32b(v.x));
    t.y = __uint_as_float(tf32b(v.y));
    t.z = __uint_as_float(tf32b(v.z));
    t.w = __uint_as_float(tf32b(v.w));
    return t;
}

// ---------------- dtype detection + index conversion (+count fused) ----------
__global__ void k_detect(const void* __restrict__ idx, int E, int N) {
    if (threadIdx.x == 0 && blockIdx.x == 0) {
        const long long* p = (const long long*)idx;
        int ok = 1;
        int cnt = 64;
        if (2 * E < 64) cnt = 2 * E;
        for (int i = 0; i < cnt; i++) {
            long long v = p[i];
            if (v < 0 || v >= (long long)N) { ok = 0; break; }
        }
        g_is64 = ok;
    }
}

__global__ void k_zero_cnt(int N) {
    int i = blockIdx.x * blockDim.x + threadIdx.x;
    if (i < N) g_cnt[i] = 0;
}

__global__ void k_prep(const void* __restrict__ idx, int E) {
    int e = blockIdx.x * blockDim.x + threadIdx.x;
    if (e >= E) return;
    int s, d;
    if (g_is64) {
        s = (int)((const long long*)idx)[e];
        d = (int)((const long long*)idx)[E + e];
    } else {
        s = ((const int*)idx)[e];
        d = ((const int*)idx)[E + e];
    }
    g_src[e] = s;
    g_dst[e] = d;
    atomicAdd(&g_cnt[d], 1);
}

// ---------------- CSR build: scan -> scatter ----------------
__global__ void k_scan_local(int N) {
    __shared__ int s[256];
    int b = blockIdx.x, t = threadIdx.x, i = b * 256 + t;
    int v = (i < N) ? g_cnt[i] + 1 : 0;
    s[t] = v;
    __syncthreads();
    for (int o = 1; o < 256; o <<= 1) {
        int x = (t >= o) ? s[t - o] : 0;
        __syncthreads();
        s[t] += x;
        __syncthreads();
    }
    if (i < N) g_scanA[i] = s[t];
    if (t == 255) g_blksum[b] = s[255];
}
__global__ void k_scan_blk(int nblk) {
    __shared__ int s[256];
    int t = threadIdx.x;
    int v = (t < nblk) ? g_blksum[t] : 0;
    s[t] = v;
    __syncthreads();
    for (int o = 1; o < 256; o <<= 1) {
        int x = (t >= o) ? s[t - o] : 0;
        __syncthreads();
        s[t] += x;
        __syncthreads();
    }
    g_blkoff[t] = s[t] - v;   // exclusive
}
__global__ void k_scan_add(int N, int T) {
    int i = blockIdx.x * blockDim.x + threadIdx.x;
    if (i < N) {
        int v = g_cnt[i] + 1;
        int off = g_scanA[i] - v + g_blkoff[i >> 8];
        g_off[i] = off;
        g_cursor[i] = off;
    }
    if (i == 0) g_off[N] = T;
}
__global__ void k_scatter(int E, int T) {
    int e = blockIdx.x * blockDim.x + threadIdx.x;
    if (e >= T) return;
    int d = (e < E) ? g_dst[e] : e - E;
    int pos = atomicAdd(&g_cursor[d], 1);
    g_eid[pos] = e;
}

// ---------------- self-loop attr from CSR (atomic-free) ----------------
__global__ void __launch_bounds__(256) k_loopcsr(const float* __restrict__ ea,
                                                 int E, int N) {
    int w = (blockIdx.x * blockDim.x + threadIdx.x) >> 5;
    int lane = threadIdx.x & 31;
    if (w >= N) return;
    int lo = g_off[w], hi = g_off[w + 1];
    float sum = 0.f;
    int cnt = 0;
    for (int p = lo; p < hi; p++) {
        int eid = g_eid[p];
        if (eid < E) { sum += ea[(size_t)eid * 32 + lane]; cnt++; }
    }
    g_loop[(size_t)w * 32 + lane] = sum / fmaxf((float)cnt, 1.f);
}

// ---------------- tf32 tensor-core GEMM (used for weight composition) --------
__global__ void __launch_bounds__(256) k_gemm_tc(const float* __restrict__ A,
                                                 const float* __restrict__ W,
                                                 const float* __restrict__ bias,
                                                 float* __restrict__ C, int M) {
    __shared__ float As[128][36];
    __shared__ float Ws[32][136];
    int tid  = threadIdx.x;
    int warp = tid >> 5, lane = tid & 31;
    int gid = lane >> 2, tig = lane & 3;
    int wr = warp & 3, wc = warp >> 2;
    int row0 = blockIdx.x * 128;

    float acc[2][8][4];
#pragma unroll
    for (int ar = 0; ar < 2; ar++)
#pragma unroll
        for (int ac = 0; ac < 8; ac++)
#pragma unroll
            for (int q = 0; q < 4; q++) acc[ar][ac][q] = 0.f;

    for (int kc = 0; kc < 128; kc += 32) {
        {
            int r  = tid >> 1;
            int k4 = (tid & 1) * 16;
            bool ok = (row0 + r) < M;
            const float* ap = A + (size_t)(row0 + r) * 128 + kc + k4;
#pragma unroll
            for (int q = 0; q < 4; q++) {
                float4 v = ok ? *(const float4*)(ap + q * 4)
                              : make_float4(0.f, 0.f, 0.f, 0.f);
                *(float4*)(&As[r][k4 + q * 4]) = cvt4(v);
            }
        }
        {
            int r  = tid >> 3;
            int c4 = (tid & 7) * 16;
            const float* wp = W + (size_t)(kc + r) * 128 + c4;
#pragma unroll
            for (int q = 0; q < 4; q++) {
                float4 v = *(const float4*)(wp + q * 4);
                *(float4*)(&Ws[r][c4 + q * 4]) = cvt4(v);
            }
        }
        __syncthreads();

#pragma unroll
        for (int ks = 0; ks < 4; ks++) {
            int k0 = ks * 8;
            unsigned int af[2][4];
#pragma unroll
            for (int ar = 0; ar < 2; ar++) {
                int rb = wr * 32 + ar * 16;
                af[ar][0] = __float_as_uint(As[rb + gid    ][k0 + tig]);
                af[ar][1] = __float_as_uint(As[rb + gid + 8][k0 + tig]);
                af[ar][2] = __float_as_uint(As[rb + gid    ][k0 + tig + 4]);
                af[ar][3] = __float_as_uint(As[rb + gid + 8][k0 + tig + 4]);
            }
#pragma unroll
            for (int ac = 0; ac < 8; ac++) {
                int cb = wc * 64 + ac * 8;
                unsigned int b0 = __float_as_uint(Ws[k0 + tig    ][cb + gid]);
                unsigned int b1 = __float_as_uint(Ws[k0 + tig + 4][cb + gid]);
                mma_tf32(acc[0][ac], af[0], b0, b1);
                mma_tf32(acc[1][ac], af[1], b0, b1);
            }
        }
        __syncthreads();
    }

#pragma unroll
    for (int ar = 0; ar < 2; ar++) {
        int rb = row0 + wr * 32 + ar * 16;
#pragma unroll
        for (int ac = 0; ac < 8; ac++) {
            int col = wc * 64 + ac * 8 + 2 * tig;
            float b0v = bias ? bias[col]     : 0.f;
            float b1v = bias ? bias[col + 1] : 0.f;
            int r0 = rb + gid, r1 = rb + gid + 8;
            if (r0 < M) {
                float2 v = make_float2(acc[ar][ac][0] + b0v, acc[ar][ac][1] + b1v);
                *(float2*)(C + (size_t)r0 * 128 + col) = v;
            }
            if (r1 < M) {
                float2 v = make_float2(acc[ar][ac][2] + b0v, acc[ar][ac][3] + b1v);
                *(float2*)(C + (size_t)r1 * 128 + col) = v;
            }
        }
    }
}

// ---------------- bias composition: blc = b_emb@Wl1 + bl1, brc = b_emb@Wr1 ----
__global__ void k_biascomp(const float* __restrict__ b_emb,
                           const float* __restrict__ Wl1,
                           const float* __restrict__ bl1,
                           const float* __restrict__ Wr1) {
    int c = threadIdx.x;   // 0..127
    const float* W = (blockIdx.x == 0) ? Wl1 : Wr1;
    float s = (blockIdx.x == 0) ? bl1[c] : 0.f;
    for (int k = 0; k < 128; k++) s += b_emb[k] * W[k * 128 + c];
    if (blockIdx.x == 0) g_blc[c] = s;
    else                 g_brc[c] = s;
}

// ---------------- fused xl/xr GEMM, software-pipelined K-chunks --------------
#define LR_SMF 13312

__global__ void __launch_bounds__(512) k_gemm_lr(const float* __restrict__ A,
                                                 const float* __restrict__ Wlp,
                                                 const float* __restrict__ blp,
                                                 const float* __restrict__ Wrp,
                                                 const float* __restrict__ brp,
                                                 float* __restrict__ Cl,
                                                 float* __restrict__ Cr, int M) {
    extern __shared__ float smlr[];
    float* As  = smlr;           // [128][36]
    float* Wsl = smlr + 4608;    // [32][136]
    float* Wsr = smlr + 8960;    // [32][136]
    int tid  = threadIdx.x;
    int warp = tid >> 5, lane = tid & 31;
    int gid = lane >> 2, tig = lane & 3;
    int wr = warp & 3, wc = warp >> 2;       // wc 0..3
    int row0 = blockIdx.x * 128;
    const float* Wsrc = (wc < 2) ? Wsl : Wsr;
    int cbase = (wc & 1) * 64;

    int rA  = tid >> 2, k4A = (tid & 3) * 8;
    int rW  = tid >> 4, c8W = (tid & 15) * 8;
    bool okA = (row0 + rA) < M;
    const float* apB = A   + (size_t)(row0 + rA) * 128 + k4A;
    const float* wlB = Wlp + (size_t)rW * 128 + c8W;
    const float* wrB = Wrp + (size_t)rW * 128 + c8W;

    float acc[2][8][4];
#pragma unroll
    for (int ar = 0; ar < 2; ar++)
#pragma unroll
        for (int ac = 0; ac < 8; ac++)
#pragma unroll
            for (int q = 0; q < 4; q++) acc[ar][ac][q] = 0.f;

    float4 pa0, pa1, pl0, pl1, pr0, pr1;
    pa0 = okA ? *(const float4*)(apB)     : make_float4(0.f, 0.f, 0.f, 0.f);
    pa1 = okA ? *(const float4*)(apB + 4) : make_float4(0.f, 0.f, 0.f, 0.f);
    pl0 = *(const float4*)(wlB);
    pl1 = *(const float4*)(wlB + 4);
    pr0 = *(const float4*)(wrB);
    pr1 = *(const float4*)(wrB + 4);

#pragma unroll
    for (int kc4 = 0; kc4 < 4; kc4++) {
        *(float4*)(&As[rA * 36 + k4A])       = cvt4(pa0);
        *(float4*)(&As[rA * 36 + k4A + 4])   = cvt4(pa1);
        *(float4*)(&Wsl[rW * 136 + c8W])     = cvt4(pl0);
        *(float4*)(&Wsl[rW * 136 + c8W + 4]) = cvt4(pl1);
        *(float4*)(&Wsr[rW * 136 + c8W])     = cvt4(pr0);
        *(float4*)(&Wsr[rW * 136 + c8W + 4]) = cvt4(pr1);
        __syncthreads();

        if (kc4 < 3) {
            int kc = (kc4 + 1) * 32;
            pa0 = okA ? *(const float4*)(apB + kc)     : make_float4(0.f, 0.f, 0.f, 0.f);
            pa1 = okA ? *(const float4*)(apB + kc + 4) : make_float4(0.f, 0.f, 0.f, 0.f);
            pl0 = *(const float4*)(wlB + (size_t)kc * 128);
            pl1 = *(const float4*)(wlB + (size_t)kc * 128 + 4);
            pr0 = *(const float4*)(wrB + (size_t)kc * 128);
            pr1 = *(const float4*)(wrB + (size_t)kc * 128 + 4);
        }

#pragma unroll
        for (int ks = 0; ks < 4; ks++) {
            int k0 = ks * 8;
            unsigned int af[2][4];
#pragma unroll
            for (int ar = 0; ar < 2; ar++) {
                int rb = wr * 32 + ar * 16;
                af[ar][0] = __float_as_uint(As[(rb + gid    ) * 36 + k0 + tig]);
                af[ar][1] = __float_as_uint(As[(rb + gid + 8) * 36 + k0 + tig]);
                af[ar][2] = __float_as_uint(As[(rb + gid    ) * 36 + k0 + tig + 4]);
                af[ar][3] = __float_as_uint(As[(rb + gid + 8) * 36 + k0 + tig + 4]);
            }
#pragma unroll
            for (int ac = 0; ac < 8; ac++) {
                int cb = cbase + ac * 8;
                unsigned int b0 = __float_as_uint(Wsrc[(k0 + tig    ) * 136 + cb + gid]);
                unsigned int b1 = __float_as_uint(Wsrc[(k0 + tig + 4) * 136 + cb + gid]);
                mma_tf32(acc[0][ac], af[0], b0, b1);
                mma_tf32(acc[1][ac], af[1], b0, b1);
            }
        }
        __syncthreads();
    }

    float* Cdst = (wc < 2) ? Cl : Cr;
    const float* bp = (wc < 2) ? blp : brp;
#pragma unroll
    for (int ar = 0; ar < 2; ar++) {
        int rb = row0 + wr * 32 + ar * 16;
#pragma unroll
        for (int ac = 0; ac < 8; ac++) {
            int col = cbase + ac * 8 + 2 * tig;
            float b0v = bp ? bp[col]     : 0.f;
            float b1v = bp ? bp[col + 1] : 0.f;
            int r0 = rb + gid, r1 = rb + gid + 8;
            if (r0 < M) {
                float2 v = make_float2(acc[ar][ac][0] + b0v, acc[ar][ac][1] + b1v);
                *(float2*)(Cdst + (size_t)r0 * 128 + col) = v;
            }
            if (r1 < M) {
                float2 v = make_float2(acc[ar][ac][2] + b0v, acc[ar][ac][3] + b1v);
                *(float2*)(Cdst + (size_t)r1 * 128 + col) = v;
            }
        }
    }
}

// ---------------- phase A: edge GEMM + score in CSR (dst-sorted) order --------
__global__ void __launch_bounds__(256, 2) k_escore(const float* __restrict__ ea,
                                                   const float* __restrict__ We,
                                                   const float* __restrict__ att,
                                                   int E, int T) {
    __shared__ float As[32][128];    // [k][edge-row]
    __shared__ float Ws[32][128];    // [k][col]
    __shared__ int   ssrc[128], sdst[128];
    __shared__ float sp[128][17];    // per-row logit partials

    int tid = threadIdx.x;
    int e0  = blockIdx.x * 128;
    int ty = tid >> 4, tx = tid & 15;

    {
        const float4* src = (const float4*)We;
        float4* dstp = (float4*)&Ws[0][0];
#pragma unroll
        for (int q = 0; q < 4; q++) dstp[tid + q * 256] = src[tid + q * 256];
    }
    if (tid < 128) {
        int p_ = e0 + tid;
        if (p_ < T) {
            int eid = g_eid[p_];
            int s, d;
            if (eid < E) { s = g_src[eid]; d = g_dst[eid]; }
            else         { s = d = eid - E; }
            ssrc[tid] = s; sdst[tid] = d;
            g_srcs[p_] = s;
        } else {
            ssrc[tid] = sdst[tid] = 0;
        }
    }
    {
        int arow = tid >> 1;
        int kb   = (tid & 1) * 16;
        int p_   = e0 + arow;
        const float* rowp = (const float*)0;
        if (p_ < T) {
            int eid = g_eid[p_];
            rowp = (eid < E) ? (ea + (size_t)eid * 32)
                             : (g_loop + (size_t)(eid - E) * 32);
        }
#pragma unroll
        for (int q = 0; q < 4; q++) {
            float4 v = rowp ? *(const float4*)(rowp + kb + q * 4)
                            : make_float4(0.f, 0.f, 0.f, 0.f);
            As[kb + q * 4 + 0][arow] = v.x;
            As[kb + q * 4 + 1][arow] = v.y;
            As[kb + q * 4 + 2][arow] = v.z;
            As[kb + q * 4 + 3][arow] = v.w;
        }
    }
    __syncthreads();

    unsigned long long acc2[8][4];
#pragma unroll
    for (int i = 0; i < 8; i++)
#pragma unroll
        for (int j = 0; j < 4; j++) acc2[i][j] = 0ULL;

#pragma unroll
    for (int k = 0; k < 32; k++) {
        float a[8];
        unsigned long long b2[4];
        *(float4*)(a)     = *(float4*)(&As[k][ty * 8]);
        *(float4*)(a + 4) = *(float4*)(&As[k][ty * 8 + 4]);
        const unsigned long long* wp = (const unsigned long long*)(&Ws[k][tx * 8]);
        b2[0] = wp[0]; b2[1] = wp[1]; b2[2] = wp[2]; b2[3] = wp[3];
#pragma unroll
        for (int i = 0; i < 8; i++) {
            unsigned long long pa = pk2(a[i], a[i]);
#pragma unroll
            for (int j = 0; j < 4; j++) fma2(acc2[i][j], pa, b2[j]);
        }
    }

    float4 at0 = *(const float4*)(att + tx * 8);
    float4 at1 = *(const float4*)(att + tx * 8 + 4);
#pragma unroll
    for (int i = 0; i < 8; i++) {
        int r = ty * 8 + i;
        int s = ssrc[r], d = sdst[r];
        const float* xlp = g_xl + (size_t)s * HID + tx * 8;
        const float* xrp = g_xr + (size_t)d * HID + tx * 8;
        float4 xl0 = *(const float4*)(xlp);
        float4 xl1 = *(const float4*)(xlp + 4);
        float4 xr0 = *(const float4*)(xrp);
        float4 xr1 = *(const float4*)(xrp + 4);
        float2 v0 = up2(acc2[i][0]);
        float2 v1 = up2(acc2[i][1]);
        float2 v2 = up2(acc2[i][2]);
        float2 v3 = up2(acc2[i][3]);
        float p = lk(xl0.x + xr0.x + v0.x) * at0.x
                + lk(xl0.y + xr0.y + v0.y) * at0.y
                + lk(xl0.z + xr0.z + v1.x) * at0.z
                + lk(xl0.w + xr0.w + v1.y) * at0.w
                + lk(xl1.x + xr1.x + v2.x) * at1.x
                + lk(xl1.y + xr1.y + v2.y) * at1.y
                + lk(xl1.z + xr1.z + v3.x) * at1.z
                + lk(xl1.w + xr1.w + v3.y) * at1.w;
        sp[r][tx] = p;
    }
    __syncthreads();

    if (tid < 128) {
        float sum = 0.f;
#pragma unroll
        for (int j = 0; j < 16; j++) sum += sp[tid][j];
        int p_ = e0 + tid;
        if (p_ < T) g_ez[p_] = __expf(sum);
    }
}

// ---------------- phase B: CSR aggregation + norm + bias + silu ----------------
__global__ void __launch_bounds__(256) k_aggr(const float* __restrict__ bo,
                                              float* __restrict__ out,
                                              int E, int N) {
    int w = (blockIdx.x * blockDim.x + threadIdx.x) >> 5;
    int lane = threadIdx.x & 31;
    if (w >= N) return;
    int lo = g_off[w], hi = g_off[w + 1];
    int c = lane * 4;
    float ax = 0.f, ay = 0.f, az = 0.f, aw = 0.f, den = 0.f;
    for (int p = lo; p < hi; p++) {
        float ez = g_ez[p];
        int s = g_srcs[p];
        float4 xl = *(const float4*)(g_xl + (size_t)s * HID + c);
        ax += ez * xl.x; ay += ez * xl.y; az += ez * xl.z; aw += ez * xl.w;
        den += ez;
    }
    float inv = 1.0f / den;
    float4 b = *(const float4*)(bo + c);
    float vx = ax * inv + b.x;
    float vy = ay * inv + b.y;
    float vz = az * inv + b.z;
    float vw = aw * inv + b.w;
    float4 o;
    o.x = vx / (1.0f + __expf(-vx));
    o.y = vy / (1.0f + __expf(-vy));
    o.z = vz / (1.0f + __expf(-vz));
    o.w = vw / (1.0f + __expf(-vw));
    *(float4*)(out + (size_t)w * HID + c) = o;
}

// ---------------- host orchestration ----------------
extern "C" void kernel_launch(void* const* d_in, const int* in_sizes, int n_in,
                              void* d_out, int out_size) {
    const float* x    = (const float*)d_in[0];
    const void*  eidx = d_in[1];
    const float* ea   = (const float*)d_in[2];
    const float* W_emb = (const float*)d_in[3];
    const float* b_emb = (const float*)d_in[4];
    const float* Wl[2]  = {(const float*)d_in[5],  (const float*)d_in[11]};
    const float* bl[2]  = {(const float*)d_in[6],  (const float*)d_in[12]};
    const float* Wr[2]  = {(const float*)d_in[7],  (const float*)d_in[13]};
    const float* We[2]  = {(const float*)d_in[8],  (const float*)d_in[14]};
    const float* att[2] = {(const float*)d_in[9],  (const float*)d_in[15]};
    const float* bo[2]  = {(const float*)d_in[10], (const float*)d_in[16]};

    int N = in_sizes[0] / HID;
    int E = in_sizes[2] / 32;
    int T = E + N;

    float *p_h, *p_xl, *p_xr, *p_wlc, *p_wrc, *p_blc, *p_brc;
    cudaGetSymbolAddress((void**)&p_h,   g_h);
    cudaGetSymbolAddress((void**)&p_xl,  g_xl);
    cudaGetSymbolAddress((void**)&p_xr,  g_xr);
    cudaGetSymbolAddress((void**)&p_wlc, g_wlc);
    cudaGetSymbolAddress((void**)&p_wrc, g_wrc);
    cudaGetSymbolAddress((void**)&p_blc, g_blc);
    cudaGetSymbolAddress((void**)&p_brc, g_brc);

    int gb_n = (N + 127) / 128;
    int nblk = (N + 255) / 256;
    int wb_n = (N * 32 + 255) / 256;

    int lr_smem = LR_SMF * 4;   // 53 KB
    cudaFuncSetAttribute(k_gemm_lr, cudaFuncAttributeMaxDynamicSharedMemorySize, lr_smem);

    // one-time resources (created on the first, non-captured correctness call;
    // only used — never created/destroyed — during graph capture)
    static cudaStream_t s2 = nullptr;
    static cudaEvent_t  evFork = nullptr, evJoin = nullptr;
    if (s2 == nullptr) {
        cudaStreamCreate(&s2);
        cudaEventCreateWithFlags(&evFork, cudaEventDisableTiming);
        cudaEventCreateWithFlags(&evJoin, cudaEventDisableTiming);
    }

    // ---- fork: CSR build chain on s2, GEMM front-end on the main stream ----
    cudaEventRecord(evFork, 0);
    cudaStreamWaitEvent(s2, evFork, 0);

    // chain B (s2): CSR build + self-loop attrs
    k_detect<<<1, 1, 0, s2>>>(eidx, E, N);
    k_zero_cnt<<<nblk, 256, 0, s2>>>(N);
    k_prep<<<(E + 255) / 256, 256, 0, s2>>>(eidx, E);
    k_scan_local<<<nblk, 256, 0, s2>>>(N);
    k_scan_blk<<<1, 256, 0, s2>>>(nblk);
    k_scan_add<<<nblk, 256, 0, s2>>>(N, T);
    k_scatter<<<(T + 255) / 256, 256, 0, s2>>>(E, T);
    k_loopcsr<<<wb_n, 256, 0, s2>>>(ea, E, N);
    cudaEventRecord(evJoin, s2);

    // chain A (main): weight composition + layer-1 node transforms
    k_gemm_tc<<<1, 256>>>(W_emb, Wl[0], nullptr, p_wlc, 128);
    k_gemm_tc<<<1, 256>>>(W_emb, Wr[0], nullptr, p_wrc, 128);
    k_biascomp<<<2, 128>>>(b_emb, Wl[0], bl[0], Wr[0]);
    k_gemm_lr<<<gb_n, 512, lr_smem>>>(x, p_wlc, p_blc, p_wrc, p_brc,
                                      p_xl, p_xr, N);

    // ---- join ----
    cudaStreamWaitEvent(0, evJoin, 0);

    int eb = (T + 127) / 128;
    // layer 1
    k_escore<<<eb, 256>>>(ea, We[0], att[0], E, T);
    k_aggr<<<wb_n, 256>>>(bo[0], p_h, E, N);
    // layer 2
    k_gemm_lr<<<gb_n, 512, lr_smem>>>(p_h, Wl[1], bl[1], Wr[1], nullptr,
                                      p_xl, p_xr, N);
    k_escore<<<eb, 256>>>(ea, We[1], att[1], E, T);
    k_aggr<<<wb_n, 256>>>(bo[1], (float*)d_out, E, N);
}

// round 15
// speedup vs baseline: 1.1732x; 1.0206x over previous
#include <cuda_runtime.h>
#include <math.h>

#define HID 128
#define NEG 0.2f
#define MAXN 50000
#define MAXE 800000
#define MAXT (MAXE + MAXN)

typedef unsigned long long ull;

// ---------------- static scratch (no allocations allowed) ----------------
__device__ float g_h  [MAXN * HID];
__device__ float g_xl [MAXN * HID];
__device__ float g_xr [MAXN * HID];
__device__ float g_loop[MAXN * 32];
__device__ float g_ez  [MAXT];     // indexed by CSR position
__device__ int   g_srcs[MAXT];     // src per CSR position (built once)
__device__ int   g_dsts[MAXT];     // dst per CSR position (built once)
__device__ int   g_src[MAXE];
__device__ int   g_dst[MAXE];
__device__ int   g_cnt[MAXN];
__device__ int   g_scanA[MAXN];
__device__ int   g_blksum[256];
__device__ int   g_blkoff[256];
__device__ int   g_off[MAXN + 1];
__device__ int   g_cursor[MAXN];
__device__ int   g_eid[MAXT];
__device__ int   g_is64;
// composed layer-1 weights (emb folded in)
__device__ float g_wlc[128 * 128];
__device__ float g_wrc[128 * 128];
__device__ float g_blc[128];
__device__ float g_brc[128];

// ---------------- small helpers ----------------
__device__ __forceinline__ float lk(float x) { return x > 0.0f ? x : NEG * x; }

__device__ __forceinline__ ull pk2(float x, float y) {
    ull r;
    asm("mov.b64 %0, {%1, %2};" : "=l"(r) : "f"(x), "f"(y));
    return r;
}
__device__ __forceinline__ void fma2(ull& d, ull a, ull b) {
    asm("fma.rn.f32x2 %0, %1, %2, %0;" : "+l"(d) : "l"(a), "l"(b));
}
__device__ __forceinline__ float2 up2(ull v) {
    float2 r;
    asm("mov.b64 {%0, %1}, %2;" : "=f"(r.x), "=f"(r.y) : "l"(v));
    return r;
}
__device__ __forceinline__ unsigned int tf32b(float x) {
    unsigned int r;
    asm("cvt.rna.tf32.f32 %0, %1;" : "=r"(r) : "f"(x));
    return r;
}
__device__ __forceinline__ void mma_tf32(float* d, const unsigned int* a,
                                         unsigned int b0, unsigned int b1) {
    asm("mma.sync.aligned.m16n8k8.row.col.f32.tf32.tf32.f32 "
        "{%0,%1,%2,%3}, {%4,%5,%6,%7}, {%8,%9}, {%0,%1,%2,%3};"
        : "+f"(d[0]), "+f"(d[1]), "+f"(d[2]), "+f"(d[3])
        : "r"(a[0]), "r"(a[1]), "r"(a[2]), "r"(a[3]), "r"(b0), "r"(b1));
}
__device__ __forceinline__ float4 cvt4(float4 v) {
    float4 t;
    t.x = __uint_as_float(tf32b(v.x));
    t.y = __uint_as_float(tf32b(v.y));
    t.z = __uint_as_float(tf32b(v.z));
    t.w = __uint_as_float(tf32b(v.w));
    return t;
}

// ---------------- dtype detection + index conversion (+count fused) ----------
__global__ void k_detect(const void* __restrict__ idx, int E, int N) {
    if (threadIdx.x == 0 && blockIdx.x == 0) {
        const long long* p = (const long long*)idx;
        int ok = 1;
        int cnt = 64;
        if (2 * E < 64) cnt = 2 * E;
        for (int i = 0; i < cnt; i++) {
            long long v = p[i];
            if (v < 0 || v >= (long long)N) { ok = 0; break; }
        }
        g_is64 = ok;
    }
}

__global__ void k_zero_cnt(int N) {
    int i = blockIdx.x * blockDim.x + threadIdx.x;
    if (i < N) g_cnt[i] = 0;
}

__global__ void k_prep(const void* __restrict__ idx, int E) {
    int e = blockIdx.x * blockDim.x + threadIdx.x;
    if (e >= E) return;
    int s, d;
    if (g_is64) {
        s = (int)((const long long*)idx)[e];
        d = (int)((const long long*)idx)[E + e];
    } else {
        s = ((const int*)idx)[e];
        d = ((const int*)idx)[E + e];
    }
    g_src[e] = s;
    g_dst[e] = d;
    atomicAdd(&g_cnt[d], 1);
}

// ---------------- CSR build: scan -> scatter ----------------
__global__ void k_scan_local(int N) {
    __shared__ int s[256];
    int b = blockIdx.x, t = threadIdx.x, i = b * 256 + t;
    int v = (i < N) ? g_cnt[i] + 1 : 0;
    s[t] = v;
    __syncthreads();
    for (int o = 1; o < 256; o <<= 1) {
        int x = (t >= o) ? s[t - o] : 0;
        __syncthreads();
        s[t] += x;
        __syncthreads();
    }
    if (i < N) g_scanA[i] = s[t];
    if (t == 255) g_blksum[b] = s[255];
}
__global__ void k_scan_blk(int nblk) {
    __shared__ int s[256];
    int t = threadIdx.x;
    int v = (t < nblk) ? g_blksum[t] : 0;
    s[t] = v;
    __syncthreads();
    for (int o = 1; o < 256; o <<= 1) {
        int x = (t >= o) ? s[t - o] : 0;
        __syncthreads();
        s[t] += x;
        __syncthreads();
    }
    g_blkoff[t] = s[t] - v;   // exclusive
}
__global__ void k_scan_add(int N, int T) {
    int i = blockIdx.x * blockDim.x + threadIdx.x;
    if (i < N) {
        int v = g_cnt[i] + 1;
        int off = g_scanA[i] - v + g_blkoff[i >> 8];
        g_off[i] = off;
        g_cursor[i] = off;
    }
    if (i == 0) g_off[N] = T;
}
// scatter also materializes CSR-positional src/dst (layer-independent)
__global__ void k_scatter(int E, int T) {
    int e = blockIdx.x * blockDim.x + threadIdx.x;
    if (e >= T) return;
    int d, s;
    if (e < E) { d = g_dst[e]; s = g_src[e]; }
    else       { d = e - E;    s = d; }
    int pos = atomicAdd(&g_cursor[d], 1);
    g_eid[pos]  = e;
    g_srcs[pos] = s;
    g_dsts[pos] = d;
}

// ---------------- self-loop attr from CSR (atomic-free) ----------------
__global__ void __launch_bounds__(256) k_loopcsr(const float* __restrict__ ea,
                                                 int E, int N) {
    int w = (blockIdx.x * blockDim.x + threadIdx.x) >> 5;
    int lane = threadIdx.x & 31;
    if (w >= N) return;
    int lo = g_off[w], hi = g_off[w + 1];
    float sum = 0.f;
    int cnt = 0;
    for (int p = lo; p < hi; p++) {
        int eid = g_eid[p];
        if (eid < E) { sum += ea[(size_t)eid * 32 + lane]; cnt++; }
    }
    g_loop[(size_t)w * 32 + lane] = sum / fmaxf((float)cnt, 1.f);
}

// ---------------- tf32 tensor-core GEMM (used for weight composition) --------
__global__ void __launch_bounds__(256) k_gemm_tc(const float* __restrict__ A,
                                                 const float* __restrict__ W,
                                                 const float* __restrict__ bias,
                                                 float* __restrict__ C, int M) {
    __shared__ float As[128][36];
    __shared__ float Ws[32][136];
    int tid  = threadIdx.x;
    int warp = tid >> 5, lane = tid & 31;
    int gid = lane >> 2, tig = lane & 3;
    int wr = warp & 3, wc = warp >> 2;
    int row0 = blockIdx.x * 128;

    float acc[2][8][4];
#pragma unroll
    for (int ar = 0; ar < 2; ar++)
#pragma unroll
        for (int ac = 0; ac < 8; ac++)
#pragma unroll
            for (int q = 0; q < 4; q++) acc[ar][ac][q] = 0.f;

    for (int kc = 0; kc < 128; kc += 32) {
        {
            int r  = tid >> 1;
            int k4 = (tid & 1) * 16;
            bool ok = (row0 + r) < M;
            const float* ap = A + (size_t)(row0 + r) * 128 + kc + k4;
#pragma unroll
            for (int q = 0; q < 4; q++) {
                float4 v = ok ? *(const float4*)(ap + q * 4)
                              : make_float4(0.f, 0.f, 0.f, 0.f);
                *(float4*)(&As[r][k4 + q * 4]) = cvt4(v);
            }
        }
        {
            int r  = tid >> 3;
            int c4 = (tid & 7) * 16;
            const float* wp = W + (size_t)(kc + r) * 128 + c4;
#pragma unroll
            for (int q = 0; q < 4; q++) {
                float4 v = *(const float4*)(wp + q * 4);
                *(float4*)(&Ws[r][c4 + q * 4]) = cvt4(v);
            }
        }
        __syncthreads();

#pragma unroll
        for (int ks = 0; ks < 4; ks++) {
            int k0 = ks * 8;
            unsigned int af[2][4];
#pragma unroll
            for (int ar = 0; ar < 2; ar++) {
                int rb = wr * 32 + ar * 16;
                af[ar][0] = __float_as_uint(As[rb + gid    ][k0 + tig]);
                af[ar][1] = __float_as_uint(As[rb + gid + 8][k0 + tig]);
                af[ar][2] = __float_as_uint(As[rb + gid    ][k0 + tig + 4]);
                af[ar][3] = __float_as_uint(As[rb + gid + 8][k0 + tig + 4]);
            }
#pragma unroll
            for (int ac = 0; ac < 8; ac++) {
                int cb = wc * 64 + ac * 8;
                unsigned int b0 = __float_as_uint(Ws[k0 + tig    ][cb + gid]);
                unsigned int b1 = __float_as_uint(Ws[k0 + tig + 4][cb + gid]);
                mma_tf32(acc[0][ac], af[0], b0, b1);
                mma_tf32(acc[1][ac], af[1], b0, b1);
            }
        }
        __syncthreads();
    }

#pragma unroll
    for (int ar = 0; ar < 2; ar++) {
        int rb = row0 + wr * 32 + ar * 16;
#pragma unroll
        for (int ac = 0; ac < 8; ac++) {
            int col = wc * 64 + ac * 8 + 2 * tig;
            float b0v = bias ? bias[col]     : 0.f;
            float b1v = bias ? bias[col + 1] : 0.f;
            int r0 = rb + gid, r1 = rb + gid + 8;
            if (r0 < M) {
                float2 v = make_float2(acc[ar][ac][0] + b0v, acc[ar][ac][1] + b1v);
                *(float2*)(C + (size_t)r0 * 128 + col) = v;
            }
            if (r1 < M) {
                float2 v = make_float2(acc[ar][ac][2] + b0v, acc[ar][ac][3] + b1v);
                *(float2*)(C + (size_t)r1 * 128 + col) = v;
            }
        }
    }
}

// ---------------- bias composition: blc = b_emb@Wl1 + bl1, brc = b_emb@Wr1 ----
__global__ void k_biascomp(const float* __restrict__ b_emb,
                           const float* __restrict__ Wl1,
                           const float* __restrict__ bl1,
                           const float* __restrict__ Wr1) {
    int c = threadIdx.x;   // 0..127
    const float* W = (blockIdx.x == 0) ? Wl1 : Wr1;
    float s = (blockIdx.x == 0) ? bl1[c] : 0.f;
    for (int k = 0; k < 128; k++) s += b_emb[k] * W[k * 128 + c];
    if (blockIdx.x == 0) g_blc[c] = s;
    else                 g_brc[c] = s;
}

// ---------------- fused xl/xr GEMM, software-pipelined K-chunks --------------
#define LR_SMF 13312

__global__ void __launch_bounds__(512) k_gemm_lr(const float* __restrict__ A,
                                                 const float* __restrict__ Wlp,
                                                 const float* __restrict__ blp,
                                                 const float* __restrict__ Wrp,
                                                 const float* __restrict__ brp,
                                                 float* __restrict__ Cl,
                                                 float* __restrict__ Cr, int M) {
    extern __shared__ float smlr[];
    float* As  = smlr;           // [128][36]
    float* Wsl = smlr + 4608;    // [32][136]
    float* Wsr = smlr + 8960;    // [32][136]
    int tid  = threadIdx.x;
    int warp = tid >> 5, lane = tid & 31;
    int gid = lane >> 2, tig = lane & 3;
    int wr = warp & 3, wc = warp >> 2;       // wc 0..3
    int row0 = blockIdx.x * 128;
    const float* Wsrc = (wc < 2) ? Wsl : Wsr;
    int cbase = (wc & 1) * 64;

    int rA  = tid >> 2, k4A = (tid & 3) * 8;
    int rW  = tid >> 4, c8W = (tid & 15) * 8;
    bool okA = (row0 + rA) < M;
    const float* apB = A   + (size_t)(row0 + rA) * 128 + k4A;
    const float* wlB = Wlp + (size_t)rW * 128 + c8W;
    const float* wrB = Wrp + (size_t)rW * 128 + c8W;

    float acc[2][8][4];
#pragma unroll
    for (int ar = 0; ar < 2; ar++)
#pragma unroll
        for (int ac = 0; ac < 8; ac++)
#pragma unroll
            for (int q = 0; q < 4; q++) acc[ar][ac][q] = 0.f;

    float4 pa0, pa1, pl0, pl1, pr0, pr1;
    pa0 = okA ? *(const float4*)(apB)     : make_float4(0.f, 0.f, 0.f, 0.f);
    pa1 = okA ? *(const float4*)(apB + 4) : make_float4(0.f, 0.f, 0.f, 0.f);
    pl0 = *(const float4*)(wlB);
    pl1 = *(const float4*)(wlB + 4);
    pr0 = *(const float4*)(wrB);
    pr1 = *(const float4*)(wrB + 4);

#pragma unroll
    for (int kc4 = 0; kc4 < 4; kc4++) {
        *(float4*)(&As[rA * 36 + k4A])       = cvt4(pa0);
        *(float4*)(&As[rA * 36 + k4A + 4])   = cvt4(pa1);
        *(float4*)(&Wsl[rW * 136 + c8W])     = cvt4(pl0);
        *(float4*)(&Wsl[rW * 136 + c8W + 4]) = cvt4(pl1);
        *(float4*)(&Wsr[rW * 136 + c8W])     = cvt4(pr0);
        *(float4*)(&Wsr[rW * 136 + c8W + 4]) = cvt4(pr1);
        __syncthreads();

        if (kc4 < 3) {
            int kc = (kc4 + 1) * 32;
            pa0 = okA ? *(const float4*)(apB + kc)     : make_float4(0.f, 0.f, 0.f, 0.f);
            pa1 = okA ? *(const float4*)(apB + kc + 4) : make_float4(0.f, 0.f, 0.f, 0.f);
            pl0 = *(const float4*)(wlB + (size_t)kc * 128);
            pl1 = *(const float4*)(wlB + (size_t)kc * 128 + 4);
            pr0 = *(const float4*)(wrB + (size_t)kc * 128);
            pr1 = *(const float4*)(wrB + (size_t)kc * 128 + 4);
        }

#pragma unroll
        for (int ks = 0; ks < 4; ks++) {
            int k0 = ks * 8;
            unsigned int af[2][4];
#pragma unroll
            for (int ar = 0; ar < 2; ar++) {
                int rb = wr * 32 + ar * 16;
                af[ar][0] = __float_as_uint(As[(rb + gid    ) * 36 + k0 + tig]);
                af[ar][1] = __float_as_uint(As[(rb + gid + 8) * 36 + k0 + tig]);
                af[ar][2] = __float_as_uint(As[(rb + gid    ) * 36 + k0 + tig + 4]);
                af[ar][3] = __float_as_uint(As[(rb + gid + 8) * 36 + k0 + tig + 4]);
            }
#pragma unroll
            for (int ac = 0; ac < 8; ac++) {
                int cb = cbase + ac * 8;
                unsigned int b0 = __float_as_uint(Wsrc[(k0 + tig    ) * 136 + cb + gid]);
                unsigned int b1 = __float_as_uint(Wsrc[(k0 + tig + 4) * 136 + cb + gid]);
                mma_tf32(acc[0][ac], af[0], b0, b1);
                mma_tf32(acc[1][ac], af[1], b0, b1);
            }
        }
        __syncthreads();
    }

    float* Cdst = (wc < 2) ? Cl : Cr;
    const float* bp = (wc < 2) ? blp : brp;
#pragma unroll
    for (int ar = 0; ar < 2; ar++) {
        int rb = row0 + wr * 32 + ar * 16;
#pragma unroll
        for (int ac = 0; ac < 8; ac++) {
            int col = cbase + ac * 8 + 2 * tig;
            float b0v = bp ? bp[col]     : 0.f;
            float b1v = bp ? bp[col + 1] : 0.f;
            int r0 = rb + gid, r1 = rb + gid + 8;
            if (r0 < M) {
                float2 v = make_float2(acc[ar][ac][0] + b0v, acc[ar][ac][1] + b1v);
                *(float2*)(Cdst + (size_t)r0 * 128 + col) = v;
            }
            if (r1 < M) {
                float2 v = make_float2(acc[ar][ac][2] + b0v, acc[ar][ac][3] + b1v);
                *(float2*)(Cdst + (size_t)r1 * 128 + col) = v;
            }
        }
    }
}

// ---------------- phase A: edge GEMM + score in CSR order ---------------------
// Dynamic smem layout (bytes):
//   As2 (ull[32][128], packed (v,v)) @0      -> 32768
//   Ws  (float[32][128])            @32768   -> 16384
//   ssrc @49152 (512), sdst @49664 (512)
//   sp (float[128][17]) @50176              -> 8704   total 58880
#define ESC_SMB 58880

__global__ void __launch_bounds__(256, 2) k_escore(const float* __restrict__ ea,
                                                   const float* __restrict__ We,
                                                   const float* __restrict__ att,
                                                   int E, int T) {
    extern __shared__ unsigned char esm[];
    ull*   As2  = (ull*)esm;                    // [k][row] packed pairs
    float* Ws   = (float*)(esm + 32768);        // [k*128 + col]
    int*   ssrc = (int*)(esm + 49152);
    int*   sdst = (int*)(esm + 49664);
    float* sp   = (float*)(esm + 50176);        // [row*17 + tx]

    int tid = threadIdx.x;
    int e0  = blockIdx.x * 128;
    int ty = tid >> 4, tx = tid & 15;

    {
        const float4* src = (const float4*)We;
        float4* dstp = (float4*)Ws;
#pragma unroll
        for (int q = 0; q < 4; q++) dstp[tid + q * 256] = src[tid + q * 256];
    }
    if (tid < 128) {
        int p_ = e0 + tid;
        if (p_ < T) {
            ssrc[tid] = g_srcs[p_];
            sdst[tid] = g_dsts[p_];
        } else {
            ssrc[tid] = sdst[tid] = 0;
        }
    }
    {
        int arow = tid >> 1;
        int kb   = (tid & 1) * 16;
        int p_   = e0 + arow;
        const float* rowp = (const float*)0;
        if (p_ < T) {
            int eid = g_eid[p_];
            rowp = (eid < E) ? (ea + (size_t)eid * 32)
                             : (g_loop + (size_t)(eid - E) * 32);
        }
#pragma unroll
        for (int q = 0; q < 4; q++) {
            float4 v = rowp ? *(const float4*)(rowp + kb + q * 4)
                            : make_float4(0.f, 0.f, 0.f, 0.f);
            As2[(size_t)(kb + q * 4 + 0) * 128 + arow] = pk2(v.x, v.x);
            As2[(size_t)(kb + q * 4 + 1) * 128 + arow] = pk2(v.y, v.y);
            As2[(size_t)(kb + q * 4 + 2) * 128 + arow] = pk2(v.z, v.z);
            As2[(size_t)(kb + q * 4 + 3) * 128 + arow] = pk2(v.w, v.w);
        }
    }
    __syncthreads();

    ull acc2[8][4];
#pragma unroll
    for (int i = 0; i < 8; i++)
#pragma unroll
        for (int j = 0; j < 4; j++) acc2[i][j] = 0ULL;

#pragma unroll
    for (int k = 0; k < 32; k++) {
        ull a2[8];
        ull b2[4];
        const ull* arp = As2 + (size_t)k * 128 + ty * 8;
#pragma unroll
        for (int i = 0; i < 8; i++) a2[i] = arp[i];
        const ull* wp = (const ull*)(Ws + (size_t)k * 128 + tx * 8);
        b2[0] = wp[0]; b2[1] = wp[1]; b2[2] = wp[2]; b2[3] = wp[3];
#pragma unroll
        for (int i = 0; i < 8; i++)
#pragma unroll
            for (int j = 0; j < 4; j++) fma2(acc2[i][j], a2[i], b2[j]);
    }

    float4 at0 = *(const float4*)(att + tx * 8);
    float4 at1 = *(const float4*)(att + tx * 8 + 4);
#pragma unroll
    for (int i = 0; i < 8; i++) {
        int r = ty * 8 + i;
        int s = ssrc[r], d = sdst[r];
        const float* xlp = g_xl + (size_t)s * HID + tx * 8;
        const float* xrp = g_xr + (size_t)d * HID + tx * 8;
        float4 xl0 = *(const float4*)(xlp);
        float4 xl1 = *(const float4*)(xlp + 4);
        float4 xr0 = *(const float4*)(xrp);
        float4 xr1 = *(const float4*)(xrp + 4);
        float2 v0 = up2(acc2[i][0]);
        float2 v1 = up2(acc2[i][1]);
        float2 v2 = up2(acc2[i][2]);
        float2 v3 = up2(acc2[i][3]);
        float p = lk(xl0.x + xr0.x + v0.x) * at0.x
                + lk(xl0.y + xr0.y + v0.y) * at0.y
                + lk(xl0.z + xr0.z + v1.x) * at0.z
                + lk(xl0.w + xr0.w + v1.y) * at0.w
                + lk(xl1.x + xr1.x + v2.x) * at1.x
                + lk(xl1.y + xr1.y + v2.y) * at1.y
                + lk(xl1.z + xr1.z + v3.x) * at1.z
                + lk(xl1.w + xr1.w + v3.y) * at1.w;
        sp[r * 17 + tx] = p;
    }
    __syncthreads();

    if (tid < 128) {
        float sum = 0.f;
#pragma unroll
        for (int j = 0; j < 16; j++) sum += sp[tid * 17 + j];
        int p_ = e0 + tid;
        if (p_ < T) g_ez[p_] = __expf(sum);
    }
}

// ---------------- phase B: CSR aggregation + norm + bias + silu ----------------
__global__ void __launch_bounds__(256) k_aggr(const float* __restrict__ bo,
                                              float* __restrict__ out,
                                              int E, int N) {
    int w = (blockIdx.x * blockDim.x + threadIdx.x) >> 5;
    int lane = threadIdx.x & 31;
    if (w >= N) return;
    int lo = g_off[w], hi = g_off[w + 1];
    int c = lane * 4;
    float ax = 0.f, ay = 0.f, az = 0.f, aw = 0.f, den = 0.f;
    for (int p = lo; p < hi; p++) {
        float ez = g_ez[p];
        int s = g_srcs[p];
        float4 xl = *(const float4*)(g_xl + (size_t)s * HID + c);
        ax += ez * xl.x; ay += ez * xl.y; az += ez * xl.z; aw += ez * xl.w;
        den += ez;
    }
    float inv = 1.0f / den;
    float4 b = *(const float4*)(bo + c);
    float vx = ax * inv + b.x;
    float vy = ay * inv + b.y;
    float vz = az * inv + b.z;
    float vw = aw * inv + b.w;
    float4 o;
    o.x = vx / (1.0f + __expf(-vx));
    o.y = vy / (1.0f + __expf(-vy));
    o.z = vz / (1.0f + __expf(-vz));
    o.w = vw / (1.0f + __expf(-vw));
    *(float4*)(out + (size_t)w * HID + c) = o;
}

// ---------------- host orchestration ----------------
extern "C" void kernel_launch(void* const* d_in, const int* in_sizes, int n_in,
                              void* d_out, int out_size) {
    const float* x    = (const float*)d_in[0];
    const void*  eidx = d_in[1];
    const float* ea   = (const float*)d_in[2];
    const float* W_emb = (const float*)d_in[3];
    const float* b_emb = (const float*)d_in[4];
    const float* Wl[2]  = {(const float*)d_in[5],  (const float*)d_in[11]};
    const float* bl[2]  = {(const float*)d_in[6],  (const float*)d_in[12]};
    const float* Wr[2]  = {(const float*)d_in[7],  (const float*)d_in[13]};
    const float* We[2]  = {(const float*)d_in[8],  (const float*)d_in[14]};
    const float* att[2] = {(const float*)d_in[9],  (const float*)d_in[15]};
    const float* bo[2]  = {(const float*)d_in[10], (const float*)d_in[16]};

    int N = in_sizes[0] / HID;
    int E = in_sizes[2] / 32;
    int T = E + N;

    float *p_h, *p_xl, *p_xr, *p_wlc, *p_wrc, *p_blc, *p_brc;
    cudaGetSymbolAddress((void**)&p_h,   g_h);
    cudaGetSymbolAddress((void**)&p_xl,  g_xl);
    cudaGetSymbolAddress((void**)&p_xr,  g_xr);
    cudaGetSymbolAddress((void**)&p_wlc, g_wlc);
    cudaGetSymbolAddress((void**)&p_wrc, g_wrc);
    cudaGetSymbolAddress((void**)&p_blc, g_blc);
    cudaGetSymbolAddress((void**)&p_brc, g_brc);

    int gb_n = (N + 127) / 128;
    int nblk = (N + 255) / 256;
    int wb_n = (N * 32 + 255) / 256;

    int lr_smem = LR_SMF * 4;   // 53 KB
    cudaFuncSetAttribute(k_gemm_lr, cudaFuncAttributeMaxDynamicSharedMemorySize, lr_smem);
    cudaFuncSetAttribute(k_escore, cudaFuncAttributeMaxDynamicSharedMemorySize, ESC_SMB);

    // one-time resources (created on the first, non-captured correctness call)
    static cudaStream_t s2 = nullptr;
    static cudaEvent_t  evFork = nullptr, evJoin = nullptr;
    if (s2 == nullptr) {
        cudaStreamCreate(&s2);
        cudaEventCreateWithFlags(&evFork, cudaEventDisableTiming);
        cudaEventCreateWithFlags(&evJoin, cudaEventDisableTiming);
    }

    // ---- fork: CSR build chain on s2, GEMM front-end on the main stream ----
    cudaEventRecord(evFork, 0);
    cudaStreamWaitEvent(s2, evFork, 0);

    // chain B (s2): CSR build + self-loop attrs
    k_detect<<<1, 1, 0, s2>>>(eidx, E, N);
    k_zero_cnt<<<nblk, 256, 0, s2>>>(N);
    k_prep<<<(E + 255) / 256, 256, 0, s2>>>(eidx, E);
    k_scan_local<<<nblk, 256, 0, s2>>>(N);
    k_scan_blk<<<1, 256, 0, s2>>>(nblk);
    k_scan_add<<<nblk, 256, 0, s2>>>(N, T);
    k_scatter<<<(T + 255) / 256, 256, 0, s2>>>(E, T);
    k_loopcsr<<<wb_n, 256, 0, s2>>>(ea, E, N);
    cudaEventRecord(evJoin, s2);

    // chain A (main): weight composition + layer-1 node transforms
    k_gemm_tc<<<1, 256>>>(W_emb, Wl[0], nullptr, p_wlc, 128);
    k_gemm_tc<<<1, 256>>>(W_emb, Wr[0], nullptr, p_wrc, 128);
    k_biascomp<<<2, 128>>>(b_emb, Wl[0], bl[0], Wr[0]);
    k_gemm_lr<<<gb_n, 512, lr_smem>>>(x, p_wlc, p_blc, p_wrc, p_brc,
                                      p_xl, p_xr, N);

    // ---- join ----
    cudaStreamWaitEvent(0, evJoin, 0);

    int eb = (T + 127) / 128;
    // layer 1
    k_escore<<<eb, 256, ESC_SMB>>>(ea, We[0], att[0], E, T);
    k_aggr<<<wb_n, 256>>>(bo[0], p_h, E, N);
    // layer 2
    k_gemm_lr<<<gb_n, 512, lr_smem>>>(p_h, Wl[1], bl[1], Wr[1], nullptr,
                                      p_xl, p_xr, N);
    k_escore<<<eb, 256, ESC_SMB>>>(ea, We[1], att[1], E, T);
    k_aggr<<<wb_n, 256>>>(bo[1], (float*)d_out, E, N);
}